// round 14
// baseline (speedup 1.0000x reference)
#include <cuda_runtime.h>
#include <cstdint>

#define N_SEQ 2048
#define C_DIM 512
#define N_BH  16

// ---- device-global scratch (no allocation allowed) ----
__device__ float g_Qi [N_BH * N_SEQ * 128];   // Q hi/lo interleaved, 1/8 folded
__device__ float g_Ki [N_BH * N_SEQ * 128];   // K hi/lo interleaved
__device__ float g_V  [N_BH * N_SEQ * 64];    // raw V [bh][n][d]
__device__ float g_P  [2 * N_SEQ * C_DIM];
__device__ float g_S  [(size_t)N_BH * N_SEQ * N_SEQ];
__device__ float g_Wi [4 * C_DIM * 2 * C_DIM];// W hi/lo interleaved [mat][n][1024]
__device__ float g_rowmax[N_BH * N_SEQ];      // per-row score max (from scores)
__device__ int   g_ci [(size_t)N_BH * N_SEQ * 256];  // candidate indices
__device__ float g_cw [(size_t)N_BH * N_SEQ * 256];  // candidate values/weights
__device__ int   g_cn [N_BH * N_SEQ];                // final support count (-1 = dense)
__device__ int   g_cnt[N_BH * N_SEQ];                // appended candidate count

// ============================ helpers ============================
__device__ __forceinline__ uint32_t f2tf(float x) {
    uint32_t r; asm("cvt.rna.tf32.f32 %0, %1;" : "=r"(r) : "f"(x)); return r;
}
__device__ __forceinline__ uint32_t smem_u32(const void* p) {
    uint32_t a;
    asm("{ .reg .u64 t; cvta.to.shared.u64 t, %1; cvt.u32.u64 %0, t; }" : "=r"(a) : "l"(p));
    return a;
}
__device__ __forceinline__ void cp16(uint32_t s, const void* g) {
    asm volatile("cp.async.cg.shared.global [%0], [%1], 16;" :: "r"(s), "l"(g) : "memory");
}
#define CP_COMMIT() asm volatile("cp.async.commit_group;" ::: "memory")
#define CP_WAIT(n)  asm volatile("cp.async.wait_group %0;" :: "n"(n) : "memory")

__device__ __forceinline__ void mma8(float* d, const uint32_t* a, const uint32_t* b) {
    asm volatile(
        "mma.sync.aligned.m16n8k8.row.col.f32.tf32.tf32.f32 "
        "{%0,%1,%2,%3}, {%4,%5,%6,%7}, {%8,%9}, {%0,%1,%2,%3};"
        : "+f"(d[0]), "+f"(d[1]), "+f"(d[2]), "+f"(d[3])
        : "r"(a[0]), "r"(a[1]), "r"(a[2]), "r"(a[3]), "r"(b[0]), "r"(b[1]));
}
__device__ __forceinline__ void cvt_hl(float x, uint32_t& h, uint32_t& l) {
    h = f2tf(x);
    l = f2tf(x - __uint_as_float(h));
}
__device__ __forceinline__ void lda_hl(uint32_t* h, uint32_t* l, const float* p, int st) {
    cvt_hl(p[0], h[0], l[0]);
    cvt_hl(p[8 * st], h[1], l[1]);
    cvt_hl(p[4], h[2], l[2]);
    cvt_hl(p[8 * st + 4], h[3], l[3]);
}
__device__ __forceinline__ void mma3(float* acc, const uint32_t* ah, const uint32_t* al,
                                     const uint32_t* bh, const uint32_t* bl) {
    mma8(acc, ah, bh);
    mma8(acc, al, bh);
    mma8(acc, ah, bl);
}
// interleaved hi/lo position: 8-group of c -> 16 floats {h(p),h(p+4),l(p),l(p+4)}x4
__device__ __forceinline__ int ilv(int c) {
    return ((c & ~7) << 1) + ((c & 3) << 2) + ((c >> 2) & 1);
}
__device__ __forceinline__ float u2f(uint32_t x) { return __uint_as_float(x); }

// =================== zero the append counters ===================
__global__ void zcnt_kernel() {
    g_cnt[blockIdx.x * 256 + threadIdx.x] = 0;
}

// =================== weight pre-split (hi/lo interleaved) ===================
__global__ void wconv_kernel(const float* __restrict__ W0, const float* __restrict__ W1,
                             const float* __restrict__ W2, const float* __restrict__ W3)
{
    const int mat = blockIdx.y;
    const float* W = (mat == 0) ? W0 : (mat == 1) ? W1 : (mat == 2) ? W2 : W3;
    const int n = blockIdx.x;
    float* dst = g_Wi + ((size_t)mat * C_DIM + n) * 1024;
    for (int c = threadIdx.x; c < C_DIM; c += blockDim.x) {
        uint32_t h, l; cvt_hl(W[n * C_DIM + c], h, l);
        const int p = ilv(c);
        dst[p] = u2f(h); dst[p + 2] = u2f(l);
    }
}

// ======================= projection GEMM (3xTF32) =======================
// Y = X @ W^T + bias.  CTA: 128m x 64n, BK=32 double-buffered; 8 warps = 16m.
// z: 0=Q interleaved (1/8 folded), 1=K interleaved, 2=raw V scatter, 3=flat out.
#define PJ_SMEM ((2 * 128 * 36 + 2 * 64 * 80) * 4)   // 77,824 B -> 2 CTAs/SM

__global__ __launch_bounds__(256, 2)
void proj_kernel(const float* __restrict__ X,
                 const float* __restrict__ b0, const float* __restrict__ b1,
                 const float* __restrict__ b2, const float* __restrict__ b3,
                 float* __restrict__ out_final, int zbase)
{
    extern __shared__ float sm[];
    float* sX[2] = { sm, sm + 128 * 36 };
    float* sW[2] = { sm + 2 * 128 * 36, sm + 2 * 128 * 36 + 64 * 80 };
    uint32_t sXa[2] = { smem_u32(sX[0]), smem_u32(sX[1]) };
    uint32_t sWa[2] = { smem_u32(sW[0]), smem_u32(sW[1]) };

    const int z = zbase + blockIdx.z;
    const float* bias = (z == 0) ? b0 : (z == 1) ? b1 : (z == 2) ? b2 : b3;
    const float* Wi = g_Wi + (size_t)z * C_DIM * 1024;

    const int tid = threadIdx.x;
    const int m0 = blockIdx.x * 128, n0 = blockIdx.y * 64;
    const int w = tid >> 5, lane = tid & 31;
    const int g = lane >> 2, t4 = lane & 3;
    const int lrX = tid >> 1, lcX = (tid & 1) * 16;   // X: 128 rows x 32 raw
    const int lrW = tid >> 2, lcW = (tid & 3) * 16;   // Wi: 64 rows x 64 ilv

    const float* xrow = X + (size_t)(m0 + lrX) * C_DIM + lcX;
    const float* wrow = Wi + (size_t)(n0 + lrW) * 1024 + lcW;

    auto prefetch = [&](int t, int buf) {
#pragma unroll
        for (int i = 0; i < 4; i++)
            cp16(sXa[buf] + (lrX * 36 + lcX + i * 4) * 4, xrow + t * 32 + i * 4);
#pragma unroll
        for (int i = 0; i < 4; i++)
            cp16(sWa[buf] + (lrW * 80 + lcW + i * 4) * 4, wrow + t * 64 + i * 4);
        CP_COMMIT();
    };

    float acc[8][4];
#pragma unroll
    for (int i = 0; i < 8; i++)
#pragma unroll
        for (int j = 0; j < 4; j++) acc[i][j] = 0.f;

    prefetch(0, 0);
    for (int t = 0; t < 16; t++) {
        const int buf = t & 1;
        if (t < 15) { prefetch(t + 1, buf ^ 1); CP_WAIT(1); }
        else        { CP_WAIT(0); }
        __syncthreads();
#pragma unroll
        for (int kf = 0; kf < 4; kf++) {
            uint32_t ah[4], al[4];
            lda_hl(ah, al, sX[buf] + (w * 16 + g) * 36 + kf * 8 + t4, 36);
#pragma unroll
            for (int nf = 0; nf < 8; nf++) {
                float4 b4 = *(const float4*)&sW[buf][(nf * 8 + g) * 80 + kf * 16 + t4 * 4];
                uint32_t bh2[2] = { __float_as_uint(b4.x), __float_as_uint(b4.y) };
                uint32_t bl2[2] = { __float_as_uint(b4.z), __float_as_uint(b4.w) };
                mma3(acc[nf], ah, al, bh2, bl2);
            }
        }
        __syncthreads();
    }

    const int m = m0 + w * 16 + g;
#pragma unroll
    for (int nf = 0; nf < 8; nf++) {
        const int j = n0 + nf * 8 + t4 * 2;
        const float bx = bias[j], by = bias[j + 1];
        float v0 = acc[nf][0] + bx, v1 = acc[nf][1] + by;   // row m
        float v2 = acc[nf][2] + bx, v3 = acc[nf][3] + by;   // row m+8
        if (z == 3) {
            *(float2*)(out_final + (size_t)m * C_DIM + j)       = make_float2(v0, v1);
            *(float2*)(out_final + (size_t)(m + 8) * C_DIM + j) = make_float2(v2, v3);
        } else {
            const int b = m >> 11, n = m & 2047;
            const int h = j >> 6, d0 = j & 63;
            const int bh = b * 8 + h;
            uint32_t hh, ll;
            if (z == 0) {          // Q interleaved, scale 1/8 folded (exact)
                const size_t r0 = ((size_t)bh * N_SEQ + n) * 128;
                const size_t r1 = r0 + 8 * 128;
                const int i0 = ilv(d0), i1 = ilv(d0 + 1);
                cvt_hl(v0 * 0.125f, hh, ll); g_Qi[r0 + i0] = u2f(hh); g_Qi[r0 + i0 + 2] = u2f(ll);
                cvt_hl(v1 * 0.125f, hh, ll); g_Qi[r0 + i1] = u2f(hh); g_Qi[r0 + i1 + 2] = u2f(ll);
                cvt_hl(v2 * 0.125f, hh, ll); g_Qi[r1 + i0] = u2f(hh); g_Qi[r1 + i0 + 2] = u2f(ll);
                cvt_hl(v3 * 0.125f, hh, ll); g_Qi[r1 + i1] = u2f(hh); g_Qi[r1 + i1 + 2] = u2f(ll);
            } else if (z == 1) {   // K interleaved
                const size_t r0 = ((size_t)bh * N_SEQ + n) * 128;
                const size_t r1 = r0 + 8 * 128;
                const int i0 = ilv(d0), i1 = ilv(d0 + 1);
                cvt_hl(v0, hh, ll); g_Ki[r0 + i0] = u2f(hh); g_Ki[r0 + i0 + 2] = u2f(ll);
                cvt_hl(v1, hh, ll); g_Ki[r0 + i1] = u2f(hh); g_Ki[r0 + i1 + 2] = u2f(ll);
                cvt_hl(v2, hh, ll); g_Ki[r1 + i0] = u2f(hh); g_Ki[r1 + i0 + 2] = u2f(ll);
                cvt_hl(v3, hh, ll); g_Ki[r1 + i1] = u2f(hh); g_Ki[r1 + i1 + 2] = u2f(ll);
            } else {               // raw V [bh][n][d]
                *(float2*)(g_V + ((size_t)bh * N_SEQ + n) * 64 + d0)     = make_float2(v0, v1);
                *(float2*)(g_V + ((size_t)bh * N_SEQ + n + 8) * 64 + d0) = make_float2(v2, v3);
            }
        }
    }
}

// ======================= scores kernel (3xTF32 + candidate collection) =======================
// Computes S = scaled Q K^T but stores ZEROS to S (the attn zero background);
// candidates (> running rowmax-1) are appended to g_ci/g_cw while still in
// registers (running thr <= final thr => no false negatives). Emits g_rowmax.
#define SC_SMEM ((128 * 144 + 2 * 32 * 144) * 4)   // 110,592 B -> 2 CTAs/SM

__global__ __launch_bounds__(256, 2)
void scores_kernel(float* __restrict__ S)
{
    extern __shared__ float sm[];
    float* sQ = sm;                                    // 128 rows x 144
    float* sK[2] = { sm + 128 * 144, sm + 128 * 144 + 32 * 144 };
    const uint32_t sQa = smem_u32(sQ);
    uint32_t sKa[2] = { smem_u32(sK[0]), smem_u32(sK[1]) };

    const int tid = threadIdx.x;
    const int bh = blockIdx.y, q0 = blockIdx.x * 128;
    const int w = tid >> 5, lane = tid & 31;
    const int g = lane >> 2, t4 = lane & 3;

    {   // Q tile: 128 rows x 128 floats
        const int lr = tid >> 1, lc = (tid & 1) * 64;
        const float* qs = g_Qi + ((size_t)bh * N_SEQ + q0 + lr) * 128 + lc;
#pragma unroll
        for (int i = 0; i < 16; i++)
            cp16(sQa + (lr * 144 + lc + i * 4) * 4, qs + i * 4);
        CP_COMMIT();
    }
    const int lrK = tid >> 3, lcK = (tid & 7) * 16;   // 32 rows x 128 floats
    const float* krow = g_Ki + ((size_t)bh * N_SEQ + lrK) * 128 + lcK;
    auto prefetchK = [&](int kt, int buf) {
        const size_t off = (size_t)kt * 32 * 128;
#pragma unroll
        for (int i = 0; i < 4; i++)
            cp16(sKa[buf] + (lrK * 144 + lcK + i * 4) * 4, krow + off + i * 4);
        CP_COMMIT();
    };

    const size_t grow0 = (size_t)bh * N_SEQ + q0 + w * 16 + g;
    const size_t grow1 = grow0 + 8;
    float m0 = -3.402823466e38f, m1 = -3.402823466e38f;   // running row maxima

    prefetchK(0, 0);
    for (int kt = 0; kt < 64; kt++) {
        const int buf = kt & 1;
        if (kt < 63) { prefetchK(kt + 1, buf ^ 1); CP_WAIT(1); }
        else         { CP_WAIT(0); }
        __syncthreads();

        float acc[4][4];
#pragma unroll
        for (int i = 0; i < 4; i++)
#pragma unroll
            for (int j = 0; j < 4; j++) acc[i][j] = 0.f;

#pragma unroll
        for (int kf = 0; kf < 8; kf++) {
            float4 qa = *(const float4*)&sQ[(w * 16 + g) * 144 + kf * 16 + t4 * 4];
            float4 qb = *(const float4*)&sQ[(w * 16 + g + 8) * 144 + kf * 16 + t4 * 4];
            uint32_t ah[4] = { __float_as_uint(qa.x), __float_as_uint(qb.x),
                               __float_as_uint(qa.y), __float_as_uint(qb.y) };
            uint32_t al[4] = { __float_as_uint(qa.z), __float_as_uint(qb.z),
                               __float_as_uint(qa.w), __float_as_uint(qb.w) };
#pragma unroll
            for (int nf = 0; nf < 4; nf++) {
                float4 kb = *(const float4*)&sK[buf][(nf * 8 + g) * 144 + kf * 16 + t4 * 4];
                uint32_t bh2[2] = { __float_as_uint(kb.x), __float_as_uint(kb.y) };
                uint32_t bl2[2] = { __float_as_uint(kb.z), __float_as_uint(kb.w) };
                mma3(acc[nf], ah, al, bh2, bl2);
            }
        }
        __syncthreads();   // all warps done with sK[buf] before it is refilled

        // update running maxima (include current tile)
#pragma unroll
        for (int nf = 0; nf < 4; nf++) {
            m0 = fmaxf(m0, fmaxf(acc[nf][0], acc[nf][1]));
            m1 = fmaxf(m1, fmaxf(acc[nf][2], acc[nf][3]));
        }
        // t4-group running max -> thresholds
        float gm0 = fmaxf(m0, __shfl_xor_sync(0xffffffffu, m0, 1));
        gm0 = fmaxf(gm0, __shfl_xor_sync(0xffffffffu, gm0, 2));
        float gm1 = fmaxf(m1, __shfl_xor_sync(0xffffffffu, m1, 1));
        gm1 = fmaxf(gm1, __shfl_xor_sync(0xffffffffu, gm1, 2));
        const float thr0 = gm0 - 1.0f, thr1 = gm1 - 1.0f;

        // append candidates (row 0)
        {
            const int colb = kt * 32 + t4 * 2;
            bool p[8];
#pragma unroll
            for (int nf = 0; nf < 4; nf++) {
                p[nf * 2]     = acc[nf][0] > thr0;
                p[nf * 2 + 1] = acc[nf][1] > thr0;
            }
            int c = 0;
#pragma unroll
            for (int j = 0; j < 8; j++) c += p[j] ? 1 : 0;
            if (c) {
                int base = atomicAdd(&g_cnt[grow0], c);
                int off = 0;
#pragma unroll
                for (int nf = 0; nf < 4; nf++) {
                    if (p[nf * 2]) {
                        if (base + off < 256) {
                            g_cw[grow0 * 256 + base + off] = acc[nf][0];
                            g_ci[grow0 * 256 + base + off] = colb + nf * 8;
                        }
                        off++;
                    }
                    if (p[nf * 2 + 1]) {
                        if (base + off < 256) {
                            g_cw[grow0 * 256 + base + off] = acc[nf][1];
                            g_ci[grow0 * 256 + base + off] = colb + nf * 8 + 1;
                        }
                        off++;
                    }
                }
            }
        }
        // append candidates (row 1)
        {
            const int colb = kt * 32 + t4 * 2;
            bool p[8];
#pragma unroll
            for (int nf = 0; nf < 4; nf++) {
                p[nf * 2]     = acc[nf][2] > thr1;
                p[nf * 2 + 1] = acc[nf][3] > thr1;
            }
            int c = 0;
#pragma unroll
            for (int j = 0; j < 8; j++) c += p[j] ? 1 : 0;
            if (c) {
                int base = atomicAdd(&g_cnt[grow1], c);
                int off = 0;
#pragma unroll
                for (int nf = 0; nf < 4; nf++) {
                    if (p[nf * 2]) {
                        if (base + off < 256) {
                            g_cw[grow1 * 256 + base + off] = acc[nf][2];
                            g_ci[grow1 * 256 + base + off] = colb + nf * 8;
                        }
                        off++;
                    }
                    if (p[nf * 2 + 1]) {
                        if (base + off < 256) {
                            g_cw[grow1 * 256 + base + off] = acc[nf][3];
                            g_ci[grow1 * 256 + base + off] = colb + nf * 8 + 1;
                        }
                        off++;
                    }
                }
            }
        }

        // store ZEROS to S (attn background); dense scores are never needed
        float* dst0 = S + grow0 * N_SEQ + kt * 32;
        float* dst1 = S + grow1 * N_SEQ + kt * 32;
        const float2 z2 = make_float2(0.f, 0.f);
#pragma unroll
        for (int nf = 0; nf < 4; nf++) {
            const int c = nf * 8 + t4 * 2;
            *(float2*)(dst0 + c) = z2;
            *(float2*)(dst1 + c) = z2;
        }
    }

    m0 = fmaxf(m0, __shfl_xor_sync(0xffffffffu, m0, 1));
    m0 = fmaxf(m0, __shfl_xor_sync(0xffffffffu, m0, 2));
    m1 = fmaxf(m1, __shfl_xor_sync(0xffffffffu, m1, 1));
    m1 = fmaxf(m1, __shfl_xor_sync(0xffffffffu, m1, 2));
    if (t4 == 0) {
        g_rowmax[grow0] = m0;
        g_rowmax[grow1] = m1;
    }
}

// ======================= tau kernel (sparse Newton + scatter) =======================
// Warp per row. Reads appended candidates, filters by final rowmax-1, Newton
// over <=8 register candidates, writes compacted (idx, w) list + scatters the
// support weights into the (already zeroed) attn. Exact fallback recomputes the
// row's scores from Q,K if appends overflowed or survivors >8/lane (g_cn = -1).
__global__ __launch_bounds__(256)
void sptau_kernel(float* __restrict__ A)
{
    const int lane = threadIdx.x & 31;
    const int warp = threadIdx.x >> 5;
    const size_t row = (size_t)blockIdx.x * 8 + warp;
    const int q = (int)(row & 2047);
    const float thr = g_rowmax[row] - 1.0f;
    const int cnt_app = g_cnt[row];
    const size_t base = row * 256;

    float cb[8]; int cx[8]; int cnt = 0;
#pragma unroll
    for (int j = 0; j < 8; j++) { cb[j] = -3.402823466e38f; cx[j] = 0; }
    if (cnt_app <= 256) {
        for (int j = lane; j < cnt_app; j += 32) {
            float v = g_cw[base + j];
            if (v > thr) {
                if (cnt < 8) {
                    int idx = g_ci[base + j];
#pragma unroll
                    for (int s = 0; s < 8; s++)
                        if (cnt == s) { cb[s] = v; cx[s] = idx; }
                }
                cnt++;
            }
        }
    }
    const bool dense = (cnt_app > 256) || __any_sync(0xffffffffu, cnt > 8);
    __syncwarp();

    float tau = thr;
    if (dense) {
        // recompute this row's scores (hi+lo reconstruct; 1/8 already folded in Q)
        const float* qi = g_Qi + row * 128;
        const float* Kb = g_Ki + (row - q) * 128;
        float* Ar = A + row * N_SEQ;
        for (int k0 = lane; k0 < N_SEQ; k0 += 32) {
            const float* ki = Kb + (size_t)k0 * 128;
            float s = 0.f;
#pragma unroll
            for (int d = 0; d < 64; d++) {
                const int p = ilv(d);
                s += (qi[p] + qi[p + 2]) * (ki[p] + ki[p + 2]);
            }
            Ar[k0] = s;
        }
        __syncwarp();
        const float4* r4 = (const float4*)Ar;
        for (int it = 0; it < 64; ++it) {
            float Ss = 0.f; int k = 0;
#pragma unroll 4
            for (int i = 0; i < 16; i++) {
                float4 v = r4[i * 32 + lane];
                float dd;
                dd = v.x - tau; if (dd > 0.f) { Ss += dd; k++; }
                dd = v.y - tau; if (dd > 0.f) { Ss += dd; k++; }
                dd = v.z - tau; if (dd > 0.f) { Ss += dd; k++; }
                dd = v.w - tau; if (dd > 0.f) { Ss += dd; k++; }
            }
#pragma unroll
            for (int o = 16; o; o >>= 1) {
                Ss += __shfl_xor_sync(0xffffffffu, Ss, o);
                k  += __shfl_xor_sync(0xffffffffu, k, o);
            }
            if (k == 0) break;
            const float delta = (Ss - 1.0f) / (float)k;
            tau += delta;
            if (fabsf(delta) < 1e-8f) break;
        }
        float4* w4 = (float4*)Ar;
#pragma unroll 4
        for (int i = 0; i < 16; i++) {
            float4 v = r4[i * 32 + lane];
            float4 o;
            o.x = fmaxf(v.x - tau, 0.f); o.y = fmaxf(v.y - tau, 0.f);
            o.z = fmaxf(v.z - tau, 0.f); o.w = fmaxf(v.w - tau, 0.f);
            w4[i * 32 + lane] = o;
        }
        if (lane == 0) g_cn[row] = -1;
        return;
    }

    // Newton over candidate registers (exact sparsemax tau)
    for (int it = 0; it < 64; ++it) {
        float Ss = 0.f; int k = 0;
#pragma unroll
        for (int j = 0; j < 8; j++) {
            float dd = cb[j] - tau;
            if (j < cnt && dd > 0.f) { Ss += dd; k++; }
        }
#pragma unroll
        for (int o = 16; o; o >>= 1) {
            Ss += __shfl_xor_sync(0xffffffffu, Ss, o);
            k  += __shfl_xor_sync(0xffffffffu, k, o);
        }
        if (k == 0) break;
        const float delta = (Ss - 1.0f) / (float)k;
        tau += delta;
        if (fabsf(delta) < 1e-8f) break;
    }

    // compacted final list (overwrites appended list; reads already in regs)
    int incl = cnt;
#pragma unroll
    for (int o = 1; o < 32; o <<= 1) {
        int t = __shfl_up_sync(0xffffffffu, incl, o);
        if (lane >= o) incl += t;
    }
    const int excl = incl - cnt;
    const int total = __shfl_sync(0xffffffffu, incl, 31);
#pragma unroll
    for (int j = 0; j < 8; j++) {
        if (j < cnt) {
            const float wv = fmaxf(cb[j] - tau, 0.f);
            g_cw[base + excl + j] = wv;
            g_ci[base + excl + j] = cx[j];
            A[row * N_SEQ + cx[j]] = wv;   // scatter onto zeroed attn
        }
    }
    if (lane == 0) g_cn[row] = total;
}

// ======================= sparse attn@V gather =======================
__global__ __launch_bounds__(256)
void spav_kernel(const float* __restrict__ A)
{
    const int lane = threadIdx.x & 31;
    const int warp = threadIdx.x >> 5;
    const size_t row = (size_t)blockIdx.x * 8 + warp;
    const int bh = (int)(row >> 11), q = (int)(row & 2047);
    const float* Vb = g_V + ((size_t)bh * N_SEQ) * 64;
    const int d = lane * 2;

    float ax = 0.f, ay = 0.f;
    const int n = g_cn[row];
    if (n >= 0) {
        const int*   ci = g_ci + row * 256;
        const float* cw = g_cw + row * 256;
        int j = 0;
        for (; j + 4 <= n; j += 4) {
            int   i0 = ci[j], i1 = ci[j+1], i2 = ci[j+2], i3 = ci[j+3];
            float w0 = cw[j], w1 = cw[j+1], w2 = cw[j+2], w3 = cw[j+3];
            float2 v0 = *(const float2*)(Vb + (size_t)i0 * 64 + d);
            float2 v1 = *(const float2*)(Vb + (size_t)i1 * 64 + d);
            float2 v2 = *(const float2*)(Vb + (size_t)i2 * 64 + d);
            float2 v3 = *(const float2*)(Vb + (size_t)i3 * 64 + d);
            ax += w0 * v0.x + w1 * v1.x + w2 * v2.x + w3 * v3.x;
            ay += w0 * v0.y + w1 * v1.y + w2 * v2.y + w3 * v3.y;
        }
        for (; j < n; j++) {
            int i0 = ci[j]; float w0 = cw[j];
            float2 v0 = *(const float2*)(Vb + (size_t)i0 * 64 + d);
            ax += w0 * v0.x; ay += w0 * v0.y;
        }
    } else {
        const float* Arow = A + row * N_SEQ;
        for (int k = 0; k < N_SEQ; k++) {
            float a = Arow[k];
            if (a != 0.f) {
                float2 v = *(const float2*)(Vb + (size_t)k * 64 + d);
                ax += a * v.x; ay += a * v.y;
            }
        }
    }

    const int b = bh >> 3, h = bh & 7;
    *(float2*)(g_P + ((size_t)(b * N_SEQ + q)) * C_DIM + h * 64 + d) = make_float2(ax, ay);
}

// ---------------------------------------------------------------------------
extern "C" void kernel_launch(void* const* d_in, const int* in_sizes, int n_in,
                              void* d_out, int out_size)
{
    const float* x  = (const float*)d_in[0];
    const float* Wq = (const float*)d_in[1];
    const float* bq = (const float*)d_in[2];
    const float* Wk = (const float*)d_in[3];
    const float* bk = (const float*)d_in[4];
    const float* Wv = (const float*)d_in[5];
    const float* bv = (const float*)d_in[6];
    const float* Wo = (const float*)d_in[7];
    const float* bo = (const float*)d_in[8];

    float *dP, *dS;
    cudaGetSymbolAddress((void**)&dP, g_P);
    cudaGetSymbolAddress((void**)&dS, g_S);

    float* out = (float*)d_out;
    const long long OUT_N = 2LL * N_SEQ * C_DIM;
    const long long ATT_N = (long long)N_BH * N_SEQ * N_SEQ;
    float* final_ptr = nullptr;
    float* attn_ptr  = nullptr;
    if ((long long)out_size >= OUT_N + ATT_N) { final_ptr = out; attn_ptr = out + OUT_N; }
    else if ((long long)out_size >= ATT_N)    { attn_ptr = out; }
    else                                      { final_ptr = out; }
    float* S = attn_ptr ? attn_ptr : dS;

    cudaFuncSetAttribute(proj_kernel,   cudaFuncAttributeMaxDynamicSharedMemorySize, PJ_SMEM);
    cudaFuncSetAttribute(scores_kernel, cudaFuncAttributeMaxDynamicSharedMemorySize, SC_SMEM);

    // pre-split weights into hi/lo interleaved; mats: 0=Wq 1=Wk 2=Wv 3=Wo
    wconv_kernel<<<dim3(C_DIM, 4), 128>>>(Wq, Wk, Wv, Wo);
    zcnt_kernel<<<(N_BH * N_SEQ) / 256, 256>>>();

    // Q/K/V projections in one launch (z selects weight + epilogue format)
    proj_kernel<<<dim3(32, 8, 3), 256, PJ_SMEM>>>(x, bq, bk, bv, bo, nullptr, 0);

    scores_kernel<<<dim3(16, 16), 256, SC_SMEM>>>(S);
    sptau_kernel<<<(N_BH * N_SEQ) / 8, 256>>>(S);
    spav_kernel<<<(N_BH * N_SEQ) / 8, 256>>>(S);

    if (final_ptr)
        proj_kernel<<<dim3(32, 8, 1), 256, PJ_SMEM>>>(dP, bq, bk, bv, bo, final_ptr, 3);
}

// round 15
// speedup vs baseline: 1.3006x; 1.3006x over previous
#include <cuda_runtime.h>
#include <cstdint>

#define N_SEQ 2048
#define C_DIM 512
#define N_BH  16

// ---- device-global scratch (no allocation allowed) ----
__device__ float g_Qi [N_BH * N_SEQ * 128];   // Q hi/lo interleaved, 1/8 folded
__device__ float g_Ki [N_BH * N_SEQ * 128];   // K hi/lo interleaved
__device__ float g_V  [N_BH * N_SEQ * 64];    // raw V [bh][n][d]
__device__ float g_P  [2 * N_SEQ * C_DIM];
__device__ float g_S  [(size_t)N_BH * N_SEQ * N_SEQ];
__device__ float g_Wi [4 * C_DIM * 2 * C_DIM];// W hi/lo interleaved [mat][n][1024]
__device__ float g_rowmax[N_BH * N_SEQ];      // per-row score max (from scores)
__device__ int   g_ci [(size_t)N_BH * N_SEQ * 256];  // candidate indices
__device__ float g_cw [(size_t)N_BH * N_SEQ * 256];  // candidate weights
__device__ int   g_cn [N_BH * N_SEQ];                // candidate count (-1 = dense)

// ============================ helpers ============================
__device__ __forceinline__ uint32_t f2tf(float x) {
    uint32_t r; asm("cvt.rna.tf32.f32 %0, %1;" : "=r"(r) : "f"(x)); return r;
}
__device__ __forceinline__ uint32_t smem_u32(const void* p) {
    uint32_t a;
    asm("{ .reg .u64 t; cvta.to.shared.u64 t, %1; cvt.u32.u64 %0, t; }" : "=r"(a) : "l"(p));
    return a;
}
__device__ __forceinline__ void cp16(uint32_t s, const void* g) {
    asm volatile("cp.async.cg.shared.global [%0], [%1], 16;" :: "r"(s), "l"(g) : "memory");
}
#define CP_COMMIT() asm volatile("cp.async.commit_group;" ::: "memory")
#define CP_WAIT(n)  asm volatile("cp.async.wait_group %0;" :: "n"(n) : "memory")

__device__ __forceinline__ void mma8(float* d, const uint32_t* a, const uint32_t* b) {
    asm volatile(
        "mma.sync.aligned.m16n8k8.row.col.f32.tf32.tf32.f32 "
        "{%0,%1,%2,%3}, {%4,%5,%6,%7}, {%8,%9}, {%0,%1,%2,%3};"
        : "+f"(d[0]), "+f"(d[1]), "+f"(d[2]), "+f"(d[3])
        : "r"(a[0]), "r"(a[1]), "r"(a[2]), "r"(a[3]), "r"(b[0]), "r"(b[1]));
}
__device__ __forceinline__ void cvt_hl(float x, uint32_t& h, uint32_t& l) {
    h = f2tf(x);
    l = f2tf(x - __uint_as_float(h));
}
__device__ __forceinline__ void lda_hl(uint32_t* h, uint32_t* l, const float* p, int st) {
    cvt_hl(p[0], h[0], l[0]);
    cvt_hl(p[8 * st], h[1], l[1]);
    cvt_hl(p[4], h[2], l[2]);
    cvt_hl(p[8 * st + 4], h[3], l[3]);
}
__device__ __forceinline__ void mma3(float* acc, const uint32_t* ah, const uint32_t* al,
                                     const uint32_t* bh, const uint32_t* bl) {
    mma8(acc, ah, bh);
    mma8(acc, al, bh);
    mma8(acc, ah, bl);
}
// interleaved hi/lo position: 8-group of c -> 16 floats {h(p),h(p+4),l(p),l(p+4)}x4
__device__ __forceinline__ int ilv(int c) {
    return ((c & ~7) << 1) + ((c & 3) << 2) + ((c >> 2) & 1);
}
__device__ __forceinline__ float u2f(uint32_t x) { return __uint_as_float(x); }

// =================== weight pre-split (hi/lo interleaved) ===================
__global__ void wconv_kernel(const float* __restrict__ W0, const float* __restrict__ W1,
                             const float* __restrict__ W2, const float* __restrict__ W3)
{
    const int mat = blockIdx.y;
    const float* W = (mat == 0) ? W0 : (mat == 1) ? W1 : (mat == 2) ? W2 : W3;
    const int n = blockIdx.x;
    float* dst = g_Wi + ((size_t)mat * C_DIM + n) * 1024;
    for (int c = threadIdx.x; c < C_DIM; c += blockDim.x) {
        uint32_t h, l; cvt_hl(W[n * C_DIM + c], h, l);
        const int p = ilv(c);
        dst[p] = u2f(h); dst[p + 2] = u2f(l);
    }
}

// ======================= projection GEMM (3xTF32) =======================
// Y = X @ W^T + bias.  CTA: 128m x 64n, BK=32 double-buffered; 8 warps = 16m.
// z: 0=Q interleaved (1/8 folded), 1=K interleaved, 2=raw V scatter, 3=flat out.
#define PJ_SMEM ((2 * 128 * 36 + 2 * 64 * 80) * 4)   // 77,824 B -> 2 CTAs/SM

__global__ __launch_bounds__(256, 2)
void proj_kernel(const float* __restrict__ X,
                 const float* __restrict__ b0, const float* __restrict__ b1,
                 const float* __restrict__ b2, const float* __restrict__ b3,
                 float* __restrict__ out_final, int zbase)
{
    extern __shared__ float sm[];
    float* sX[2] = { sm, sm + 128 * 36 };
    float* sW[2] = { sm + 2 * 128 * 36, sm + 2 * 128 * 36 + 64 * 80 };
    uint32_t sXa[2] = { smem_u32(sX[0]), smem_u32(sX[1]) };
    uint32_t sWa[2] = { smem_u32(sW[0]), smem_u32(sW[1]) };

    const int z = zbase + blockIdx.z;
    const float* bias = (z == 0) ? b0 : (z == 1) ? b1 : (z == 2) ? b2 : b3;
    const float* Wi = g_Wi + (size_t)z * C_DIM * 1024;

    const int tid = threadIdx.x;
    const int m0 = blockIdx.x * 128, n0 = blockIdx.y * 64;
    const int w = tid >> 5, lane = tid & 31;
    const int g = lane >> 2, t4 = lane & 3;
    const int lrX = tid >> 1, lcX = (tid & 1) * 16;   // X: 128 rows x 32 raw
    const int lrW = tid >> 2, lcW = (tid & 3) * 16;   // Wi: 64 rows x 64 ilv

    const float* xrow = X + (size_t)(m0 + lrX) * C_DIM + lcX;
    const float* wrow = Wi + (size_t)(n0 + lrW) * 1024 + lcW;

    auto prefetch = [&](int t, int buf) {
#pragma unroll
        for (int i = 0; i < 4; i++)
            cp16(sXa[buf] + (lrX * 36 + lcX + i * 4) * 4, xrow + t * 32 + i * 4);
#pragma unroll
        for (int i = 0; i < 4; i++)
            cp16(sWa[buf] + (lrW * 80 + lcW + i * 4) * 4, wrow + t * 64 + i * 4);
        CP_COMMIT();
    };

    float acc[8][4];
#pragma unroll
    for (int i = 0; i < 8; i++)
#pragma unroll
        for (int j = 0; j < 4; j++) acc[i][j] = 0.f;

    prefetch(0, 0);
    for (int t = 0; t < 16; t++) {
        const int buf = t & 1;
        if (t < 15) { prefetch(t + 1, buf ^ 1); CP_WAIT(1); }
        else        { CP_WAIT(0); }
        __syncthreads();
#pragma unroll
        for (int kf = 0; kf < 4; kf++) {
            uint32_t ah[4], al[4];
            lda_hl(ah, al, sX[buf] + (w * 16 + g) * 36 + kf * 8 + t4, 36);
#pragma unroll
            for (int nf = 0; nf < 8; nf++) {
                float4 b4 = *(const float4*)&sW[buf][(nf * 8 + g) * 80 + kf * 16 + t4 * 4];
                uint32_t bh2[2] = { __float_as_uint(b4.x), __float_as_uint(b4.y) };
                uint32_t bl2[2] = { __float_as_uint(b4.z), __float_as_uint(b4.w) };
                mma3(acc[nf], ah, al, bh2, bl2);
            }
        }
        __syncthreads();
    }

    const int m = m0 + w * 16 + g;
#pragma unroll
    for (int nf = 0; nf < 8; nf++) {
        const int j = n0 + nf * 8 + t4 * 2;
        const float bx = bias[j], by = bias[j + 1];
        float v0 = acc[nf][0] + bx, v1 = acc[nf][1] + by;   // row m
        float v2 = acc[nf][2] + bx, v3 = acc[nf][3] + by;   // row m+8
        if (z == 3) {
            *(float2*)(out_final + (size_t)m * C_DIM + j)       = make_float2(v0, v1);
            *(float2*)(out_final + (size_t)(m + 8) * C_DIM + j) = make_float2(v2, v3);
        } else {
            const int b = m >> 11, n = m & 2047;
            const int h = j >> 6, d0 = j & 63;
            const int bh = b * 8 + h;
            uint32_t hh, ll;
            if (z == 0) {          // Q interleaved, scale 1/8 folded (exact)
                const size_t r0 = ((size_t)bh * N_SEQ + n) * 128;
                const size_t r1 = r0 + 8 * 128;
                const int i0 = ilv(d0), i1 = ilv(d0 + 1);
                cvt_hl(v0 * 0.125f, hh, ll); g_Qi[r0 + i0] = u2f(hh); g_Qi[r0 + i0 + 2] = u2f(ll);
                cvt_hl(v1 * 0.125f, hh, ll); g_Qi[r0 + i1] = u2f(hh); g_Qi[r0 + i1 + 2] = u2f(ll);
                cvt_hl(v2 * 0.125f, hh, ll); g_Qi[r1 + i0] = u2f(hh); g_Qi[r1 + i0 + 2] = u2f(ll);
                cvt_hl(v3 * 0.125f, hh, ll); g_Qi[r1 + i1] = u2f(hh); g_Qi[r1 + i1 + 2] = u2f(ll);
            } else if (z == 1) {   // K interleaved
                const size_t r0 = ((size_t)bh * N_SEQ + n) * 128;
                const size_t r1 = r0 + 8 * 128;
                const int i0 = ilv(d0), i1 = ilv(d0 + 1);
                cvt_hl(v0, hh, ll); g_Ki[r0 + i0] = u2f(hh); g_Ki[r0 + i0 + 2] = u2f(ll);
                cvt_hl(v1, hh, ll); g_Ki[r0 + i1] = u2f(hh); g_Ki[r0 + i1 + 2] = u2f(ll);
                cvt_hl(v2, hh, ll); g_Ki[r1 + i0] = u2f(hh); g_Ki[r1 + i0 + 2] = u2f(ll);
                cvt_hl(v3, hh, ll); g_Ki[r1 + i1] = u2f(hh); g_Ki[r1 + i1 + 2] = u2f(ll);
            } else {               // raw V [bh][n][d]
                *(float2*)(g_V + ((size_t)bh * N_SEQ + n) * 64 + d0)     = make_float2(v0, v1);
                *(float2*)(g_V + ((size_t)bh * N_SEQ + n + 8) * 64 + d0) = make_float2(v2, v3);
            }
        }
    }
}

// ======================= scores kernel v3 (3xTF32, Q in registers) =======================
// S[q,:] = scaled Q K^T (scale folded into Q). CTA: 128 threads / 64 q-rows.
// Q fragments loaded ONCE from global into registers (loop-invariant over k);
// K double-buffered 32-row tiles in smem (pad 132, conflict-free). Emits rowmax.
#define SC_SMEM (2 * 32 * 132 * 4)   // 33,792 B

__global__ __launch_bounds__(128, 3)
void scores_kernel(float* __restrict__ S)
{
    extern __shared__ float sm[];
    float* sK[2] = { sm, sm + 32 * 132 };
    uint32_t sKa[2] = { smem_u32(sK[0]), smem_u32(sK[1]) };

    const int tid = threadIdx.x;
    const int bh = blockIdx.y, q0 = blockIdx.x * 64;
    const int w = tid >> 5, lane = tid & 31;
    const int g = lane >> 2, t4 = lane & 3;

    // ---- Q fragments -> registers (once) ----
    uint32_t ah[8][4], al[8][4];
    {
        const float* q0p = g_Qi + ((size_t)bh * N_SEQ + q0 + w * 16 + g) * 128;
        const float* q1p = q0p + 8 * 128;
#pragma unroll
        for (int kf = 0; kf < 8; kf++) {
            float4 qa = *(const float4*)(q0p + kf * 16 + t4 * 4);
            float4 qb = *(const float4*)(q1p + kf * 16 + t4 * 4);
            ah[kf][0] = __float_as_uint(qa.x); ah[kf][1] = __float_as_uint(qb.x);
            ah[kf][2] = __float_as_uint(qa.y); ah[kf][3] = __float_as_uint(qb.y);
            al[kf][0] = __float_as_uint(qa.z); al[kf][1] = __float_as_uint(qb.z);
            al[kf][2] = __float_as_uint(qa.w); al[kf][3] = __float_as_uint(qb.w);
        }
    }

    // K loader: 128 threads cover 32 rows x 128 floats (8 float4 each)
    const int lrK = tid >> 2, lcK = (tid & 3) * 32;
    const float* krow = g_Ki + ((size_t)bh * N_SEQ + lrK) * 128 + lcK;
    auto prefetchK = [&](int kt, int buf) {
        const size_t off = (size_t)kt * 32 * 128;
#pragma unroll
        for (int i = 0; i < 8; i++)
            cp16(sKa[buf] + (lrK * 132 + lcK + i * 4) * 4, krow + off + i * 4);
        CP_COMMIT();
    };

    const size_t grow0 = (size_t)bh * N_SEQ + q0 + w * 16 + g;
    const size_t grow1 = grow0 + 8;
    float m0 = -3.402823466e38f, m1 = -3.402823466e38f;

    prefetchK(0, 0);
    for (int kt = 0; kt < 64; kt++) {
        const int buf = kt & 1;
        if (kt < 63) { prefetchK(kt + 1, buf ^ 1); CP_WAIT(1); }
        else         { CP_WAIT(0); }
        __syncthreads();

        float acc[4][4];
#pragma unroll
        for (int i = 0; i < 4; i++)
#pragma unroll
            for (int j = 0; j < 4; j++) acc[i][j] = 0.f;

#pragma unroll
        for (int kf = 0; kf < 8; kf++) {
#pragma unroll
            for (int nf = 0; nf < 4; nf++) {
                float4 kb = *(const float4*)&sK[buf][(nf * 8 + g) * 132 + kf * 16 + t4 * 4];
                uint32_t bh2[2] = { __float_as_uint(kb.x), __float_as_uint(kb.y) };
                uint32_t bl2[2] = { __float_as_uint(kb.z), __float_as_uint(kb.w) };
                mma3(acc[nf], ah[kf], al[kf], bh2, bl2);
            }
        }
        __syncthreads();   // all warps done with sK[buf] before it is refilled

        float* dst0 = S + grow0 * N_SEQ + kt * 32;
        float* dst1 = S + grow1 * N_SEQ + kt * 32;
#pragma unroll
        for (int nf = 0; nf < 4; nf++) {
            m0 = fmaxf(m0, fmaxf(acc[nf][0], acc[nf][1]));
            m1 = fmaxf(m1, fmaxf(acc[nf][2], acc[nf][3]));
            const int c = nf * 8 + t4 * 2;
            *(float2*)(dst0 + c) = make_float2(acc[nf][0], acc[nf][1]);
            *(float2*)(dst1 + c) = make_float2(acc[nf][2], acc[nf][3]);
        }
    }

    m0 = fmaxf(m0, __shfl_xor_sync(0xffffffffu, m0, 1));
    m0 = fmaxf(m0, __shfl_xor_sync(0xffffffffu, m0, 2));
    m1 = fmaxf(m1, __shfl_xor_sync(0xffffffffu, m1, 1));
    m1 = fmaxf(m1, __shfl_xor_sync(0xffffffffu, m1, 2));
    if (t4 == 0) {
        g_rowmax[grow0] = m0;
        g_rowmax[grow1] = m1;
    }
}

// ======================= sparsemax kernel (R11-proven v4) =======================
// Row per warp. Single read pass: filter candidates (> rowmax-1) into shared
// (value + index), Newton over <=8 register candidates -> tau. Writeback needs
// NO read: zeros + scatter. Emits compacted (idx, w) list. Dense fallback = -1.
__global__ __launch_bounds__(256)
void spmax_kernel(float* __restrict__ A)
{
    __shared__ float cv[8 * 8 * 32];
    __shared__ int   cx[8 * 8 * 32];
    const int lane = threadIdx.x & 31;
    const int warp = threadIdx.x >> 5;
    const size_t row = (size_t)blockIdx.x * 8 + warp;
    const float4* r4 = (const float4*)(A + row * N_SEQ);
    float4* w4 = (float4*)(A + row * N_SEQ);

    const float thr = g_rowmax[row] - 1.0f;

    float* cwv = cv + warp * 256 + lane;
    int*   cwx = cx + warp * 256 + lane;
    int cnt = 0;
#pragma unroll 4
    for (int i = 0; i < 16; i++) {
        float4 v = r4[i * 32 + lane];
        float e[4] = { v.x, v.y, v.z, v.w };
#pragma unroll
        for (int c = 0; c < 4; c++) {
            if (e[c] > thr) {
                if (cnt < 8) { cwv[cnt * 32] = e[c]; cwx[cnt * 32] = (i * 32 + lane) * 4 + c; }
                cnt++;
            }
        }
    }
    __syncwarp();

    float tau = thr;
    if (__ballot_sync(0xffffffffu, cnt > 8)) {
        for (int it = 0; it < 64; ++it) {
            float Ss = 0.f; int k = 0;
#pragma unroll 4
            for (int i = 0; i < 16; i++) {
                float4 v = r4[i * 32 + lane];
                float dd;
                dd = v.x - tau; if (dd > 0.f) { Ss += dd; k++; }
                dd = v.y - tau; if (dd > 0.f) { Ss += dd; k++; }
                dd = v.z - tau; if (dd > 0.f) { Ss += dd; k++; }
                dd = v.w - tau; if (dd > 0.f) { Ss += dd; k++; }
            }
#pragma unroll
            for (int o = 16; o; o >>= 1) {
                Ss += __shfl_xor_sync(0xffffffffu, Ss, o);
                k  += __shfl_xor_sync(0xffffffffu, k, o);
            }
            if (k == 0) break;
            const float delta = (Ss - 1.0f) / (float)k;
            tau += delta;
            if (fabsf(delta) < 1e-8f) break;
        }
#pragma unroll 4
        for (int i = 0; i < 16; i++) {
            float4 v = r4[i * 32 + lane];
            float4 o;
            o.x = fmaxf(v.x - tau, 0.f); o.y = fmaxf(v.y - tau, 0.f);
            o.z = fmaxf(v.z - tau, 0.f); o.w = fmaxf(v.w - tau, 0.f);
            w4[i * 32 + lane] = o;
        }
        if (lane == 0) g_cn[row] = -1;
    } else {
        float cb[8];
#pragma unroll
        for (int j = 0; j < 8; j++) cb[j] = cwv[j * 32];
        for (int it = 0; it < 64; ++it) {
            float Ss = 0.f; int k = 0;
#pragma unroll
            for (int j = 0; j < 8; j++) {
                float dd = cb[j] - tau;
                if (j < cnt && dd > 0.f) { Ss += dd; k++; }
            }
#pragma unroll
            for (int o = 16; o; o >>= 1) {
                Ss += __shfl_xor_sync(0xffffffffu, Ss, o);
                k  += __shfl_xor_sync(0xffffffffu, k, o);
            }
            if (k == 0) break;
            const float delta = (Ss - 1.0f) / (float)k;
            tau += delta;
            if (fabsf(delta) < 1e-8f) break;
        }

        int incl = cnt;
#pragma unroll
        for (int o = 1; o < 32; o <<= 1) {
            int t = __shfl_up_sync(0xffffffffu, incl, o);
            if (lane >= o) incl += t;
        }
        const int excl = incl - cnt;
        const int total = __shfl_sync(0xffffffffu, incl, 31);
        const size_t base = row * 256;
#pragma unroll
        for (int j = 0; j < 8; j++) {
            if (j < cnt) {
                g_cw[base + excl + j] = fmaxf(cb[j] - tau, 0.f);
                g_ci[base + excl + j] = cwx[j * 32];
            }
        }
        if (lane == 0) g_cn[row] = total;

        const float4 z = make_float4(0.f, 0.f, 0.f, 0.f);
#pragma unroll 4
        for (int i = 0; i < 16; i++) w4[i * 32 + lane] = z;
#pragma unroll
        for (int j = 0; j < 8; j++) {
            if (j < cnt)
                A[row * N_SEQ + cwx[j * 32]] = fmaxf(cb[j] - tau, 0.f);
        }
    }
}

// ======================= sparse attn@V gather =======================
__global__ __launch_bounds__(256)
void spav_kernel(const float* __restrict__ A)
{
    const int lane = threadIdx.x & 31;
    const int warp = threadIdx.x >> 5;
    const size_t row = (size_t)blockIdx.x * 8 + warp;
    const int bh = (int)(row >> 11), q = (int)(row & 2047);
    const float* Vb = g_V + ((size_t)bh * N_SEQ) * 64;
    const int d = lane * 2;

    float ax = 0.f, ay = 0.f;
    const int n = g_cn[row];
    if (n >= 0) {
        const int*   ci = g_ci + row * 256;
        const float* cw = g_cw + row * 256;
        int j = 0;
        for (; j + 4 <= n; j += 4) {
            int   i0 = ci[j], i1 = ci[j+1], i2 = ci[j+2], i3 = ci[j+3];
            float w0 = cw[j], w1 = cw[j+1], w2 = cw[j+2], w3 = cw[j+3];
            float2 v0 = *(const float2*)(Vb + (size_t)i0 * 64 + d);
            float2 v1 = *(const float2*)(Vb + (size_t)i1 * 64 + d);
            float2 v2 = *(const float2*)(Vb + (size_t)i2 * 64 + d);
            float2 v3 = *(const float2*)(Vb + (size_t)i3 * 64 + d);
            ax += w0 * v0.x + w1 * v1.x + w2 * v2.x + w3 * v3.x;
            ay += w0 * v0.y + w1 * v1.y + w2 * v2.y + w3 * v3.y;
        }
        for (; j < n; j++) {
            int i0 = ci[j]; float w0 = cw[j];
            float2 v0 = *(const float2*)(Vb + (size_t)i0 * 64 + d);
            ax += w0 * v0.x; ay += w0 * v0.y;
        }
    } else {
        const float* Arow = A + row * N_SEQ;
        for (int k = 0; k < N_SEQ; k++) {
            float a = Arow[k];
            if (a != 0.f) {
                float2 v = *(const float2*)(Vb + (size_t)k * 64 + d);
                ax += a * v.x; ay += a * v.y;
            }
        }
    }

    const int b = bh >> 3, h = bh & 7;
    *(float2*)(g_P + ((size_t)(b * N_SEQ + q)) * C_DIM + h * 64 + d) = make_float2(ax, ay);
}

// ---------------------------------------------------------------------------
extern "C" void kernel_launch(void* const* d_in, const int* in_sizes, int n_in,
                              void* d_out, int out_size)
{
    const float* x  = (const float*)d_in[0];
    const float* Wq = (const float*)d_in[1];
    const float* bq = (const float*)d_in[2];
    const float* Wk = (const float*)d_in[3];
    const float* bk = (const float*)d_in[4];
    const float* Wv = (const float*)d_in[5];
    const float* bv = (const float*)d_in[6];
    const float* Wo = (const float*)d_in[7];
    const float* bo = (const float*)d_in[8];

    float *dP, *dS;
    cudaGetSymbolAddress((void**)&dP, g_P);
    cudaGetSymbolAddress((void**)&dS, g_S);

    float* out = (float*)d_out;
    const long long OUT_N = 2LL * N_SEQ * C_DIM;
    const long long ATT_N = (long long)N_BH * N_SEQ * N_SEQ;
    float* final_ptr = nullptr;
    float* attn_ptr  = nullptr;
    if ((long long)out_size >= OUT_N + ATT_N) { final_ptr = out; attn_ptr = out + OUT_N; }
    else if ((long long)out_size >= ATT_N)    { attn_ptr = out; }
    else                                      { final_ptr = out; }
    float* S = attn_ptr ? attn_ptr : dS;

    cudaFuncSetAttribute(proj_kernel,   cudaFuncAttributeMaxDynamicSharedMemorySize, PJ_SMEM);
    cudaFuncSetAttribute(scores_kernel, cudaFuncAttributeMaxDynamicSharedMemorySize, SC_SMEM);

    // pre-split weights into hi/lo interleaved; mats: 0=Wq 1=Wk 2=Wv 3=Wo
    wconv_kernel<<<dim3(C_DIM, 4), 128>>>(Wq, Wk, Wv, Wo);

    // Q/K/V projections in one launch (z selects weight + epilogue format)
    proj_kernel<<<dim3(32, 8, 3), 256, PJ_SMEM>>>(x, bq, bk, bv, bo, nullptr, 0);

    scores_kernel<<<dim3(32, 16), 128, SC_SMEM>>>(S);
    spmax_kernel<<<(N_BH * N_SEQ) / 8, 256>>>(S);
    spav_kernel<<<(N_BH * N_SEQ) / 8, 256>>>(S);

    if (final_ptr)
        proj_kernel<<<dim3(32, 8, 1), 256, PJ_SMEM>>>(dP, bq, bk, bv, bo, final_ptr, 3);
}

// round 16
// speedup vs baseline: 1.4059x; 1.0810x over previous
#include <cuda_runtime.h>
#include <cstdint>

#define N_SEQ 2048
#define C_DIM 512
#define N_BH  16

// ---- device-global scratch (no allocation allowed) ----
__device__ float g_Qi [N_BH * N_SEQ * 128];   // Q hi/lo interleaved, 1/8 folded
__device__ float g_Ki [N_BH * N_SEQ * 128];   // K hi/lo interleaved
__device__ float g_V  [N_BH * N_SEQ * 64];    // raw V [bh][n][d]
__device__ float g_P  [2 * N_SEQ * C_DIM];
__device__ float g_S  [(size_t)N_BH * N_SEQ * N_SEQ];
__device__ float g_Wi [4 * C_DIM * 2 * C_DIM];// W hi/lo interleaved [mat][n][1024]
__device__ float g_rowmax[N_BH * N_SEQ];      // per-row score max (from scores)
__device__ int   g_ci [(size_t)N_BH * N_SEQ * 256];  // candidate indices
__device__ float g_cw [(size_t)N_BH * N_SEQ * 256];  // candidate weights
__device__ int   g_cn [N_BH * N_SEQ];                // candidate count (-1 = dense)

// ============================ helpers ============================
__device__ __forceinline__ uint32_t f2tf(float x) {
    uint32_t r; asm("cvt.rna.tf32.f32 %0, %1;" : "=r"(r) : "f"(x)); return r;
}
__device__ __forceinline__ uint32_t smem_u32(const void* p) {
    uint32_t a;
    asm("{ .reg .u64 t; cvta.to.shared.u64 t, %1; cvt.u32.u64 %0, t; }" : "=r"(a) : "l"(p));
    return a;
}
__device__ __forceinline__ void cp16(uint32_t s, const void* g) {
    asm volatile("cp.async.cg.shared.global [%0], [%1], 16;" :: "r"(s), "l"(g) : "memory");
}
#define CP_COMMIT() asm volatile("cp.async.commit_group;" ::: "memory")
#define CP_WAIT(n)  asm volatile("cp.async.wait_group %0;" :: "n"(n) : "memory")

__device__ __forceinline__ void mma8(float* d, const uint32_t* a, const uint32_t* b) {
    asm volatile(
        "mma.sync.aligned.m16n8k8.row.col.f32.tf32.tf32.f32 "
        "{%0,%1,%2,%3}, {%4,%5,%6,%7}, {%8,%9}, {%0,%1,%2,%3};"
        : "+f"(d[0]), "+f"(d[1]), "+f"(d[2]), "+f"(d[3])
        : "r"(a[0]), "r"(a[1]), "r"(a[2]), "r"(a[3]), "r"(b[0]), "r"(b[1]));
}
__device__ __forceinline__ void cvt_hl(float x, uint32_t& h, uint32_t& l) {
    h = f2tf(x);
    l = f2tf(x - __uint_as_float(h));
}
__device__ __forceinline__ void lda_hl(uint32_t* h, uint32_t* l, const float* p, int st) {
    cvt_hl(p[0], h[0], l[0]);
    cvt_hl(p[8 * st], h[1], l[1]);
    cvt_hl(p[4], h[2], l[2]);
    cvt_hl(p[8 * st + 4], h[3], l[3]);
}
__device__ __forceinline__ void mma3(float* acc, const uint32_t* ah, const uint32_t* al,
                                     const uint32_t* bh, const uint32_t* bl) {
    mma8(acc, ah, bh);
    mma8(acc, al, bh);
    mma8(acc, ah, bl);
}
// interleaved hi/lo position: 8-group of c -> 16 floats {h(p),h(p+4),l(p),l(p+4)}x4
__device__ __forceinline__ int ilv(int c) {
    return ((c & ~7) << 1) + ((c & 3) << 2) + ((c >> 2) & 1);
}
__device__ __forceinline__ float u2f(uint32_t x) { return __uint_as_float(x); }

// =================== weight pre-split (hi/lo interleaved) ===================
__global__ void wconv_kernel(const float* __restrict__ W0, const float* __restrict__ W1,
                             const float* __restrict__ W2, const float* __restrict__ W3)
{
    const int mat = blockIdx.y;
    const float* W = (mat == 0) ? W0 : (mat == 1) ? W1 : (mat == 2) ? W2 : W3;
    const int n = blockIdx.x;
    float* dst = g_Wi + ((size_t)mat * C_DIM + n) * 1024;
    for (int c = threadIdx.x; c < C_DIM; c += blockDim.x) {
        uint32_t h, l; cvt_hl(W[n * C_DIM + c], h, l);
        const int p = ilv(c);
        dst[p] = u2f(h); dst[p + 2] = u2f(l);
    }
}

// ======================= projection GEMM (3xTF32) =======================
// Y = X @ W^T + bias.  CTA: 128m x 64n, BK=32 double-buffered; 8 warps = 16m.
// z: 0=Q interleaved (1/8 folded), 1=K interleaved, 2=raw V scatter, 3=flat out.
#define PJ_SMEM ((2 * 128 * 36 + 2 * 64 * 80) * 4)   // 77,824 B -> 2 CTAs/SM

__global__ __launch_bounds__(256, 2)
void proj_kernel(const float* __restrict__ X,
                 const float* __restrict__ b0, const float* __restrict__ b1,
                 const float* __restrict__ b2, const float* __restrict__ b3,
                 float* __restrict__ out_final, int zbase)
{
    extern __shared__ float sm[];
    float* sX[2] = { sm, sm + 128 * 36 };
    float* sW[2] = { sm + 2 * 128 * 36, sm + 2 * 128 * 36 + 64 * 80 };
    uint32_t sXa[2] = { smem_u32(sX[0]), smem_u32(sX[1]) };
    uint32_t sWa[2] = { smem_u32(sW[0]), smem_u32(sW[1]) };

    const int z = zbase + blockIdx.z;
    const float* bias = (z == 0) ? b0 : (z == 1) ? b1 : (z == 2) ? b2 : b3;
    const float* Wi = g_Wi + (size_t)z * C_DIM * 1024;

    const int tid = threadIdx.x;
    const int m0 = blockIdx.x * 128, n0 = blockIdx.y * 64;
    const int w = tid >> 5, lane = tid & 31;
    const int g = lane >> 2, t4 = lane & 3;
    const int lrX = tid >> 1, lcX = (tid & 1) * 16;   // X: 128 rows x 32 raw
    const int lrW = tid >> 2, lcW = (tid & 3) * 16;   // Wi: 64 rows x 64 ilv

    const float* xrow = X + (size_t)(m0 + lrX) * C_DIM + lcX;
    const float* wrow = Wi + (size_t)(n0 + lrW) * 1024 + lcW;

    auto prefetch = [&](int t, int buf) {
#pragma unroll
        for (int i = 0; i < 4; i++)
            cp16(sXa[buf] + (lrX * 36 + lcX + i * 4) * 4, xrow + t * 32 + i * 4);
#pragma unroll
        for (int i = 0; i < 4; i++)
            cp16(sWa[buf] + (lrW * 80 + lcW + i * 4) * 4, wrow + t * 64 + i * 4);
        CP_COMMIT();
    };

    float acc[8][4];
#pragma unroll
    for (int i = 0; i < 8; i++)
#pragma unroll
        for (int j = 0; j < 4; j++) acc[i][j] = 0.f;

    prefetch(0, 0);
    for (int t = 0; t < 16; t++) {
        const int buf = t & 1;
        if (t < 15) { prefetch(t + 1, buf ^ 1); CP_WAIT(1); }
        else        { CP_WAIT(0); }
        __syncthreads();
#pragma unroll
        for (int kf = 0; kf < 4; kf++) {
            uint32_t ah[4], al[4];
            lda_hl(ah, al, sX[buf] + (w * 16 + g) * 36 + kf * 8 + t4, 36);
#pragma unroll
            for (int nf = 0; nf < 8; nf++) {
                float4 b4 = *(const float4*)&sW[buf][(nf * 8 + g) * 80 + kf * 16 + t4 * 4];
                uint32_t bh2[2] = { __float_as_uint(b4.x), __float_as_uint(b4.y) };
                uint32_t bl2[2] = { __float_as_uint(b4.z), __float_as_uint(b4.w) };
                mma3(acc[nf], ah, al, bh2, bl2);
            }
        }
        __syncthreads();
    }

    const int m = m0 + w * 16 + g;
#pragma unroll
    for (int nf = 0; nf < 8; nf++) {
        const int j = n0 + nf * 8 + t4 * 2;
        const float bx = bias[j], by = bias[j + 1];
        float v0 = acc[nf][0] + bx, v1 = acc[nf][1] + by;   // row m
        float v2 = acc[nf][2] + bx, v3 = acc[nf][3] + by;   // row m+8
        if (z == 3) {
            *(float2*)(out_final + (size_t)m * C_DIM + j)       = make_float2(v0, v1);
            *(float2*)(out_final + (size_t)(m + 8) * C_DIM + j) = make_float2(v2, v3);
        } else {
            const int b = m >> 11, n = m & 2047;
            const int h = j >> 6, d0 = j & 63;
            const int bh = b * 8 + h;
            uint32_t hh, ll;
            if (z == 0) {          // Q interleaved, scale 1/8 folded (exact)
                const size_t r0 = ((size_t)bh * N_SEQ + n) * 128;
                const size_t r1 = r0 + 8 * 128;
                const int i0 = ilv(d0), i1 = ilv(d0 + 1);
                cvt_hl(v0 * 0.125f, hh, ll); g_Qi[r0 + i0] = u2f(hh); g_Qi[r0 + i0 + 2] = u2f(ll);
                cvt_hl(v1 * 0.125f, hh, ll); g_Qi[r0 + i1] = u2f(hh); g_Qi[r0 + i1 + 2] = u2f(ll);
                cvt_hl(v2 * 0.125f, hh, ll); g_Qi[r1 + i0] = u2f(hh); g_Qi[r1 + i0 + 2] = u2f(ll);
                cvt_hl(v3 * 0.125f, hh, ll); g_Qi[r1 + i1] = u2f(hh); g_Qi[r1 + i1 + 2] = u2f(ll);
            } else if (z == 1) {   // K interleaved
                const size_t r0 = ((size_t)bh * N_SEQ + n) * 128;
                const size_t r1 = r0 + 8 * 128;
                const int i0 = ilv(d0), i1 = ilv(d0 + 1);
                cvt_hl(v0, hh, ll); g_Ki[r0 + i0] = u2f(hh); g_Ki[r0 + i0 + 2] = u2f(ll);
                cvt_hl(v1, hh, ll); g_Ki[r0 + i1] = u2f(hh); g_Ki[r0 + i1 + 2] = u2f(ll);
                cvt_hl(v2, hh, ll); g_Ki[r1 + i0] = u2f(hh); g_Ki[r1 + i0 + 2] = u2f(ll);
                cvt_hl(v3, hh, ll); g_Ki[r1 + i1] = u2f(hh); g_Ki[r1 + i1 + 2] = u2f(ll);
            } else {               // raw V [bh][n][d]
                *(float2*)(g_V + ((size_t)bh * N_SEQ + n) * 64 + d0)     = make_float2(v0, v1);
                *(float2*)(g_V + ((size_t)bh * N_SEQ + n + 8) * 64 + d0) = make_float2(v2, v3);
            }
        }
    }
}

// ======================= scores kernel (3xTF32, R11-proven) =======================
// S[q,:] = scaled Q K^T (scale folded into Q).  CTA: (bh, 128 q), 64 token-tiles
// of 32, double-buffered. Emits per-row max into g_rowmax (fused, ~free).
#define SC_SMEM ((128 * 144 + 2 * 32 * 144) * 4)   // 110,592 B -> 2 CTAs/SM

__global__ __launch_bounds__(256, 2)
void scores_kernel(float* __restrict__ S)
{
    extern __shared__ float sm[];
    float* sQ = sm;                                    // 128 rows x 144
    float* sK[2] = { sm + 128 * 144, sm + 128 * 144 + 32 * 144 };
    const uint32_t sQa = smem_u32(sQ);
    uint32_t sKa[2] = { smem_u32(sK[0]), smem_u32(sK[1]) };

    const int tid = threadIdx.x;
    const int bh = blockIdx.y, q0 = blockIdx.x * 128;
    const int w = tid >> 5, lane = tid & 31;
    const int g = lane >> 2, t4 = lane & 3;

    {   // Q tile: 128 rows x 128 floats
        const int lr = tid >> 1, lc = (tid & 1) * 64;
        const float* qs = g_Qi + ((size_t)bh * N_SEQ + q0 + lr) * 128 + lc;
#pragma unroll
        for (int i = 0; i < 16; i++)
            cp16(sQa + (lr * 144 + lc + i * 4) * 4, qs + i * 4);
        CP_COMMIT();
    }
    const int lrK = tid >> 3, lcK = (tid & 7) * 16;   // 32 rows x 128 floats
    const float* krow = g_Ki + ((size_t)bh * N_SEQ + lrK) * 128 + lcK;
    auto prefetchK = [&](int kt, int buf) {
        const size_t off = (size_t)kt * 32 * 128;
#pragma unroll
        for (int i = 0; i < 4; i++)
            cp16(sKa[buf] + (lrK * 144 + lcK + i * 4) * 4, krow + off + i * 4);
        CP_COMMIT();
    };

    const size_t grow0 = (size_t)bh * N_SEQ + q0 + w * 16 + g;
    const size_t grow1 = grow0 + 8;
    float m0 = -3.402823466e38f, m1 = -3.402823466e38f;   // row maxima

    prefetchK(0, 0);
    for (int kt = 0; kt < 64; kt++) {
        const int buf = kt & 1;
        if (kt < 63) { prefetchK(kt + 1, buf ^ 1); CP_WAIT(1); }
        else         { CP_WAIT(0); }
        __syncthreads();

        float acc[4][4];
#pragma unroll
        for (int i = 0; i < 4; i++)
#pragma unroll
            for (int j = 0; j < 4; j++) acc[i][j] = 0.f;

#pragma unroll
        for (int kf = 0; kf < 8; kf++) {
            float4 qa = *(const float4*)&sQ[(w * 16 + g) * 144 + kf * 16 + t4 * 4];
            float4 qb = *(const float4*)&sQ[(w * 16 + g + 8) * 144 + kf * 16 + t4 * 4];
            uint32_t ah[4] = { __float_as_uint(qa.x), __float_as_uint(qb.x),
                               __float_as_uint(qa.y), __float_as_uint(qb.y) };
            uint32_t al[4] = { __float_as_uint(qa.z), __float_as_uint(qb.z),
                               __float_as_uint(qa.w), __float_as_uint(qb.w) };
#pragma unroll
            for (int nf = 0; nf < 4; nf++) {
                float4 kb = *(const float4*)&sK[buf][(nf * 8 + g) * 144 + kf * 16 + t4 * 4];
                uint32_t bh2[2] = { __float_as_uint(kb.x), __float_as_uint(kb.y) };
                uint32_t bl2[2] = { __float_as_uint(kb.z), __float_as_uint(kb.w) };
                mma3(acc[nf], ah, al, bh2, bl2);
            }
        }
        __syncthreads();   // all warps done with sK[buf] before it is refilled

        float* dst0 = S + grow0 * N_SEQ + kt * 32;
        float* dst1 = S + grow1 * N_SEQ + kt * 32;
#pragma unroll
        for (int nf = 0; nf < 4; nf++) {
            m0 = fmaxf(m0, fmaxf(acc[nf][0], acc[nf][1]));
            m1 = fmaxf(m1, fmaxf(acc[nf][2], acc[nf][3]));
            const int c = nf * 8 + t4 * 2;
            *(float2*)(dst0 + c) = make_float2(acc[nf][0], acc[nf][1]);
            *(float2*)(dst1 + c) = make_float2(acc[nf][2], acc[nf][3]);
        }
    }

    m0 = fmaxf(m0, __shfl_xor_sync(0xffffffffu, m0, 1));
    m0 = fmaxf(m0, __shfl_xor_sync(0xffffffffu, m0, 2));
    m1 = fmaxf(m1, __shfl_xor_sync(0xffffffffu, m1, 1));
    m1 = fmaxf(m1, __shfl_xor_sync(0xffffffffu, m1, 2));
    if (t4 == 0) {
        g_rowmax[grow0] = m0;
        g_rowmax[grow1] = m1;
    }
}

// ======================= sparsemax kernel (v6: float4 early-out) =======================
// Row per warp. Filter pass: per-float4 max vs thr (3 FMAX + 1 setp, FMA pipe)
// skips all per-element work for the >99% of float4s with no candidate; actual
// candidates insert into per-warp shared slots in original order (identical tau).
// Newton over <=8 register candidates; writeback = zeros (no read) + scatter;
// emits compacted (idx,w) list. Exact dense fallback (g_cn = -1).
__global__ __launch_bounds__(256)
void spmax_kernel(float* __restrict__ A)
{
    __shared__ float cv[8 * 8 * 32];
    __shared__ int   cx[8 * 8 * 32];
    const int lane = threadIdx.x & 31;
    const int warp = threadIdx.x >> 5;
    const size_t row = (size_t)blockIdx.x * 8 + warp;
    const float4* r4 = (const float4*)(A + row * N_SEQ);
    float4* w4 = (float4*)(A + row * N_SEQ);

    const float thr = g_rowmax[row] - 1.0f;

    float* cwv = cv + warp * 256 + lane;
    int*   cwx = cx + warp * 256 + lane;
    int cnt = 0;
#pragma unroll 4
    for (int i = 0; i < 16; i++) {
        float4 v = r4[i * 32 + lane];
        const float mx = fmaxf(fmaxf(v.x, v.y), fmaxf(v.z, v.w));
        if (mx > thr) {   // rare: this float4 holds >=1 candidate
            float e[4] = { v.x, v.y, v.z, v.w };
#pragma unroll
            for (int c = 0; c < 4; c++) {
                if (e[c] > thr) {
                    if (cnt < 8) { cwv[cnt * 32] = e[c]; cwx[cnt * 32] = (i * 32 + lane) * 4 + c; }
                    cnt++;
                }
            }
        }
    }
    __syncwarp();

    float tau = thr;
    if (__ballot_sync(0xffffffffu, cnt > 8)) {
        for (int it = 0; it < 64; ++it) {
            float Ss = 0.f; int k = 0;
#pragma unroll 4
            for (int i = 0; i < 16; i++) {
                float4 v = r4[i * 32 + lane];
                float dd;
                dd = v.x - tau; if (dd > 0.f) { Ss += dd; k++; }
                dd = v.y - tau; if (dd > 0.f) { Ss += dd; k++; }
                dd = v.z - tau; if (dd > 0.f) { Ss += dd; k++; }
                dd = v.w - tau; if (dd > 0.f) { Ss += dd; k++; }
            }
#pragma unroll
            for (int o = 16; o; o >>= 1) {
                Ss += __shfl_xor_sync(0xffffffffu, Ss, o);
                k  += __shfl_xor_sync(0xffffffffu, k, o);
            }
            if (k == 0) break;
            const float delta = (Ss - 1.0f) / (float)k;
            tau += delta;
            if (fabsf(delta) < 1e-8f) break;
        }
#pragma unroll 4
        for (int i = 0; i < 16; i++) {
            float4 v = r4[i * 32 + lane];
            float4 o;
            o.x = fmaxf(v.x - tau, 0.f); o.y = fmaxf(v.y - tau, 0.f);
            o.z = fmaxf(v.z - tau, 0.f); o.w = fmaxf(v.w - tau, 0.f);
            w4[i * 32 + lane] = o;
        }
        if (lane == 0) g_cn[row] = -1;
    } else {
        float cb[8];
#pragma unroll
        for (int j = 0; j < 8; j++) cb[j] = cwv[j * 32];
        for (int it = 0; it < 64; ++it) {
            float Ss = 0.f; int k = 0;
#pragma unroll
            for (int j = 0; j < 8; j++) {
                float dd = cb[j] - tau;
                if (j < cnt && dd > 0.f) { Ss += dd; k++; }
            }
#pragma unroll
            for (int o = 16; o; o >>= 1) {
                Ss += __shfl_xor_sync(0xffffffffu, Ss, o);
                k  += __shfl_xor_sync(0xffffffffu, k, o);
            }
            if (k == 0) break;
            const float delta = (Ss - 1.0f) / (float)k;
            tau += delta;
            if (fabsf(delta) < 1e-8f) break;
        }

        int incl = cnt;
#pragma unroll
        for (int o = 1; o < 32; o <<= 1) {
            int t = __shfl_up_sync(0xffffffffu, incl, o);
            if (lane >= o) incl += t;
        }
        const int excl = incl - cnt;
        const int total = __shfl_sync(0xffffffffu, incl, 31);
        const size_t base = row * 256;
#pragma unroll
        for (int j = 0; j < 8; j++) {
            if (j < cnt) {
                g_cw[base + excl + j] = fmaxf(cb[j] - tau, 0.f);
                g_ci[base + excl + j] = cwx[j * 32];
            }
        }
        if (lane == 0) g_cn[row] = total;

        const float4 z = make_float4(0.f, 0.f, 0.f, 0.f);
#pragma unroll 4
        for (int i = 0; i < 16; i++) w4[i * 32 + lane] = z;
#pragma unroll
        for (int j = 0; j < 8; j++) {
            if (j < cnt)
                A[row * N_SEQ + cwx[j * 32]] = fmaxf(cb[j] - tau, 0.f);
        }
    }
}

// ======================= sparse attn@V gather =======================
__global__ __launch_bounds__(256)
void spav_kernel(const float* __restrict__ A)
{
    const int lane = threadIdx.x & 31;
    const int warp = threadIdx.x >> 5;
    const size_t row = (size_t)blockIdx.x * 8 + warp;
    const int bh = (int)(row >> 11), q = (int)(row & 2047);
    const float* Vb = g_V + ((size_t)bh * N_SEQ) * 64;
    const int d = lane * 2;

    float ax = 0.f, ay = 0.f;
    const int n = g_cn[row];
    if (n >= 0) {
        const int*   ci = g_ci + row * 256;
        const float* cw = g_cw + row * 256;
        int j = 0;
        for (; j + 4 <= n; j += 4) {
            int   i0 = ci[j], i1 = ci[j+1], i2 = ci[j+2], i3 = ci[j+3];
            float w0 = cw[j], w1 = cw[j+1], w2 = cw[j+2], w3 = cw[j+3];
            float2 v0 = *(const float2*)(Vb + (size_t)i0 * 64 + d);
            float2 v1 = *(const float2*)(Vb + (size_t)i1 * 64 + d);
            float2 v2 = *(const float2*)(Vb + (size_t)i2 * 64 + d);
            float2 v3 = *(const float2*)(Vb + (size_t)i3 * 64 + d);
            ax += w0 * v0.x + w1 * v1.x + w2 * v2.x + w3 * v3.x;
            ay += w0 * v0.y + w1 * v1.y + w2 * v2.y + w3 * v3.y;
        }
        for (; j < n; j++) {
            int i0 = ci[j]; float w0 = cw[j];
            float2 v0 = *(const float2*)(Vb + (size_t)i0 * 64 + d);
            ax += w0 * v0.x; ay += w0 * v0.y;
        }
    } else {
        const float* Arow = A + row * N_SEQ;
        for (int k = 0; k < N_SEQ; k++) {
            float a = Arow[k];
            if (a != 0.f) {
                float2 v = *(const float2*)(Vb + (size_t)k * 64 + d);
                ax += a * v.x; ay += a * v.y;
            }
        }
    }

    const int b = bh >> 3, h = bh & 7;
    *(float2*)(g_P + ((size_t)(b * N_SEQ + q)) * C_DIM + h * 64 + d) = make_float2(ax, ay);
}

// ---------------------------------------------------------------------------
extern "C" void kernel_launch(void* const* d_in, const int* in_sizes, int n_in,
                              void* d_out, int out_size)
{
    const float* x  = (const float*)d_in[0];
    const float* Wq = (const float*)d_in[1];
    const float* bq = (const float*)d_in[2];
    const float* Wk = (const float*)d_in[3];
    const float* bk = (const float*)d_in[4];
    const float* Wv = (const float*)d_in[5];
    const float* bv = (const float*)d_in[6];
    const float* Wo = (const float*)d_in[7];
    const float* bo = (const float*)d_in[8];

    float *dP, *dS;
    cudaGetSymbolAddress((void**)&dP, g_P);
    cudaGetSymbolAddress((void**)&dS, g_S);

    float* out = (float*)d_out;
    const long long OUT_N = 2LL * N_SEQ * C_DIM;
    const long long ATT_N = (long long)N_BH * N_SEQ * N_SEQ;
    float* final_ptr = nullptr;
    float* attn_ptr  = nullptr;
    if ((long long)out_size >= OUT_N + ATT_N) { final_ptr = out; attn_ptr = out + OUT_N; }
    else if ((long long)out_size >= ATT_N)    { attn_ptr = out; }
    else                                      { final_ptr = out; }
    float* S = attn_ptr ? attn_ptr : dS;

    cudaFuncSetAttribute(proj_kernel,   cudaFuncAttributeMaxDynamicSharedMemorySize, PJ_SMEM);
    cudaFuncSetAttribute(scores_kernel, cudaFuncAttributeMaxDynamicSharedMemorySize, SC_SMEM);

    // pre-split weights into hi/lo interleaved; mats: 0=Wq 1=Wk 2=Wv 3=Wo
    wconv_kernel<<<dim3(C_DIM, 4), 128>>>(Wq, Wk, Wv, Wo);

    // Q/K/V projections in one launch (z selects weight + epilogue format)
    proj_kernel<<<dim3(32, 8, 3), 256, PJ_SMEM>>>(x, bq, bk, bv, bo, nullptr, 0);

    scores_kernel<<<dim3(16, 16), 256, SC_SMEM>>>(S);
    spmax_kernel<<<(N_BH * N_SEQ) / 8, 256>>>(S);
    spav_kernel<<<(N_BH * N_SEQ) / 8, 256>>>(S);

    if (final_ptr)
        proj_kernel<<<dim3(32, 8, 1), 256, PJ_SMEM>>>(dP, bq, bk, bv, bo, final_ptr, 3);
}

// round 17
// speedup vs baseline: 1.5223x; 1.0827x over previous
#include <cuda_runtime.h>
#include <cstdint>

#define N_SEQ 2048
#define C_DIM 512
#define N_BH  16

// ---- device-global scratch (no allocation allowed) ----
__device__ float g_Qi [N_BH * N_SEQ * 128];   // Q hi/lo interleaved, 1/8 folded
__device__ float g_Ki [N_BH * N_SEQ * 128];   // K hi/lo interleaved
__device__ float g_V  [N_BH * N_SEQ * 64];    // raw V [bh][n][d]
__device__ float g_P  [2 * N_SEQ * C_DIM];
__device__ float g_S  [(size_t)N_BH * N_SEQ * N_SEQ];
__device__ float g_Wi [4 * C_DIM * 2 * C_DIM];// W hi/lo interleaved [mat][n][1024]
__device__ float g_rowmax[N_BH * N_SEQ];      // per-row score max (from scores)
__device__ int   g_ci [(size_t)N_BH * N_SEQ * 256];  // candidate indices
__device__ float g_cw [(size_t)N_BH * N_SEQ * 256];  // candidate weights
__device__ int   g_cn [N_BH * N_SEQ];                // candidate count (-1 = dense)

// ============================ helpers ============================
__device__ __forceinline__ uint32_t f2tf(float x) {
    uint32_t r; asm("cvt.rna.tf32.f32 %0, %1;" : "=r"(r) : "f"(x)); return r;
}
__device__ __forceinline__ uint32_t smem_u32(const void* p) {
    uint32_t a;
    asm("{ .reg .u64 t; cvta.to.shared.u64 t, %1; cvt.u32.u64 %0, t; }" : "=r"(a) : "l"(p));
    return a;
}
__device__ __forceinline__ void cp16(uint32_t s, const void* g) {
    asm volatile("cp.async.cg.shared.global [%0], [%1], 16;" :: "r"(s), "l"(g) : "memory");
}
#define CP_COMMIT() asm volatile("cp.async.commit_group;" ::: "memory")
#define CP_WAIT(n)  asm volatile("cp.async.wait_group %0;" :: "n"(n) : "memory")

__device__ __forceinline__ void mma8(float* d, const uint32_t* a, const uint32_t* b) {
    asm volatile(
        "mma.sync.aligned.m16n8k8.row.col.f32.tf32.tf32.f32 "
        "{%0,%1,%2,%3}, {%4,%5,%6,%7}, {%8,%9}, {%0,%1,%2,%3};"
        : "+f"(d[0]), "+f"(d[1]), "+f"(d[2]), "+f"(d[3])
        : "r"(a[0]), "r"(a[1]), "r"(a[2]), "r"(a[3]), "r"(b[0]), "r"(b[1]));
}
__device__ __forceinline__ void cvt_hl(float x, uint32_t& h, uint32_t& l) {
    h = f2tf(x);
    l = f2tf(x - __uint_as_float(h));
}
__device__ __forceinline__ void lda_hl(uint32_t* h, uint32_t* l, const float* p, int st) {
    cvt_hl(p[0], h[0], l[0]);
    cvt_hl(p[8 * st], h[1], l[1]);
    cvt_hl(p[4], h[2], l[2]);
    cvt_hl(p[8 * st + 4], h[3], l[3]);
}
__device__ __forceinline__ void mma3(float* acc, const uint32_t* ah, const uint32_t* al,
                                     const uint32_t* bh, const uint32_t* bl) {
    mma8(acc, ah, bh);
    mma8(acc, al, bh);
    mma8(acc, ah, bl);
}
// interleaved hi/lo position: 8-group of c -> 16 floats {h(p),h(p+4),l(p),l(p+4)}x4
__device__ __forceinline__ int ilv(int c) {
    return ((c & ~7) << 1) + ((c & 3) << 2) + ((c >> 2) & 1);
}
__device__ __forceinline__ float u2f(uint32_t x) { return __uint_as_float(x); }

// =================== weight pre-split (hi/lo interleaved) ===================
__global__ void wconv_kernel(const float* __restrict__ W0, const float* __restrict__ W1,
                             const float* __restrict__ W2, const float* __restrict__ W3)
{
    const int mat = blockIdx.y;
    const float* W = (mat == 0) ? W0 : (mat == 1) ? W1 : (mat == 2) ? W2 : W3;
    const int n = blockIdx.x;
    float* dst = g_Wi + ((size_t)mat * C_DIM + n) * 1024;
    for (int c = threadIdx.x; c < C_DIM; c += blockDim.x) {
        uint32_t h, l; cvt_hl(W[n * C_DIM + c], h, l);
        const int p = ilv(c);
        dst[p] = u2f(h); dst[p + 2] = u2f(l);
    }
}

// ======================= projection GEMM (3xTF32) =======================
// Y = X @ W^T + bias.  CTA: 128m x 64n, BK=32 double-buffered; 8 warps = 16m.
// z: 0=Q interleaved (1/8 folded), 1=K interleaved, 2=raw V scatter, 3=flat out.
#define PJ_SMEM ((2 * 128 * 36 + 2 * 64 * 80) * 4)   // 77,824 B -> 2 CTAs/SM

__global__ __launch_bounds__(256, 2)
void proj_kernel(const float* __restrict__ X,
                 const float* __restrict__ b0, const float* __restrict__ b1,
                 const float* __restrict__ b2, const float* __restrict__ b3,
                 float* __restrict__ out_final, int zbase)
{
    extern __shared__ float sm[];
    float* sX[2] = { sm, sm + 128 * 36 };
    float* sW[2] = { sm + 2 * 128 * 36, sm + 2 * 128 * 36 + 64 * 80 };
    uint32_t sXa[2] = { smem_u32(sX[0]), smem_u32(sX[1]) };
    uint32_t sWa[2] = { smem_u32(sW[0]), smem_u32(sW[1]) };

    const int z = zbase + blockIdx.z;
    const float* bias = (z == 0) ? b0 : (z == 1) ? b1 : (z == 2) ? b2 : b3;
    const float* Wi = g_Wi + (size_t)z * C_DIM * 1024;

    const int tid = threadIdx.x;
    const int m0 = blockIdx.x * 128, n0 = blockIdx.y * 64;
    const int w = tid >> 5, lane = tid & 31;
    const int g = lane >> 2, t4 = lane & 3;
    const int lrX = tid >> 1, lcX = (tid & 1) * 16;   // X: 128 rows x 32 raw
    const int lrW = tid >> 2, lcW = (tid & 3) * 16;   // Wi: 64 rows x 64 ilv

    const float* xrow = X + (size_t)(m0 + lrX) * C_DIM + lcX;
    const float* wrow = Wi + (size_t)(n0 + lrW) * 1024 + lcW;

    auto prefetch = [&](int t, int buf) {
#pragma unroll
        for (int i = 0; i < 4; i++)
            cp16(sXa[buf] + (lrX * 36 + lcX + i * 4) * 4, xrow + t * 32 + i * 4);
#pragma unroll
        for (int i = 0; i < 4; i++)
            cp16(sWa[buf] + (lrW * 80 + lcW + i * 4) * 4, wrow + t * 64 + i * 4);
        CP_COMMIT();
    };

    float acc[8][4];
#pragma unroll
    for (int i = 0; i < 8; i++)
#pragma unroll
        for (int j = 0; j < 4; j++) acc[i][j] = 0.f;

    prefetch(0, 0);
    for (int t = 0; t < 16; t++) {
        const int buf = t & 1;
        if (t < 15) { prefetch(t + 1, buf ^ 1); CP_WAIT(1); }
        else        { CP_WAIT(0); }
        __syncthreads();
#pragma unroll
        for (int kf = 0; kf < 4; kf++) {
            uint32_t ah[4], al[4];
            lda_hl(ah, al, sX[buf] + (w * 16 + g) * 36 + kf * 8 + t4, 36);
#pragma unroll
            for (int nf = 0; nf < 8; nf++) {
                float4 b4 = *(const float4*)&sW[buf][(nf * 8 + g) * 80 + kf * 16 + t4 * 4];
                uint32_t bh2[2] = { __float_as_uint(b4.x), __float_as_uint(b4.y) };
                uint32_t bl2[2] = { __float_as_uint(b4.z), __float_as_uint(b4.w) };
                mma3(acc[nf], ah, al, bh2, bl2);
            }
        }
        __syncthreads();
    }

    const int m = m0 + w * 16 + g;
#pragma unroll
    for (int nf = 0; nf < 8; nf++) {
        const int j = n0 + nf * 8 + t4 * 2;
        const float bx = bias[j], by = bias[j + 1];
        float v0 = acc[nf][0] + bx, v1 = acc[nf][1] + by;   // row m
        float v2 = acc[nf][2] + bx, v3 = acc[nf][3] + by;   // row m+8
        if (z == 3) {
            *(float2*)(out_final + (size_t)m * C_DIM + j)       = make_float2(v0, v1);
            *(float2*)(out_final + (size_t)(m + 8) * C_DIM + j) = make_float2(v2, v3);
        } else {
            const int b = m >> 11, n = m & 2047;
            const int h = j >> 6, d0 = j & 63;
            const int bh = b * 8 + h;
            uint32_t hh, ll;
            if (z == 0) {          // Q interleaved, scale 1/8 folded (exact)
                const size_t r0 = ((size_t)bh * N_SEQ + n) * 128;
                const size_t r1 = r0 + 8 * 128;
                const int i0 = ilv(d0), i1 = ilv(d0 + 1);
                cvt_hl(v0 * 0.125f, hh, ll); g_Qi[r0 + i0] = u2f(hh); g_Qi[r0 + i0 + 2] = u2f(ll);
                cvt_hl(v1 * 0.125f, hh, ll); g_Qi[r0 + i1] = u2f(hh); g_Qi[r0 + i1 + 2] = u2f(ll);
                cvt_hl(v2 * 0.125f, hh, ll); g_Qi[r1 + i0] = u2f(hh); g_Qi[r1 + i0 + 2] = u2f(ll);
                cvt_hl(v3 * 0.125f, hh, ll); g_Qi[r1 + i1] = u2f(hh); g_Qi[r1 + i1 + 2] = u2f(ll);
            } else if (z == 1) {   // K interleaved
                const size_t r0 = ((size_t)bh * N_SEQ + n) * 128;
                const size_t r1 = r0 + 8 * 128;
                const int i0 = ilv(d0), i1 = ilv(d0 + 1);
                cvt_hl(v0, hh, ll); g_Ki[r0 + i0] = u2f(hh); g_Ki[r0 + i0 + 2] = u2f(ll);
                cvt_hl(v1, hh, ll); g_Ki[r0 + i1] = u2f(hh); g_Ki[r0 + i1 + 2] = u2f(ll);
                cvt_hl(v2, hh, ll); g_Ki[r1 + i0] = u2f(hh); g_Ki[r1 + i0 + 2] = u2f(ll);
                cvt_hl(v3, hh, ll); g_Ki[r1 + i1] = u2f(hh); g_Ki[r1 + i1 + 2] = u2f(ll);
            } else {               // raw V [bh][n][d]
                *(float2*)(g_V + ((size_t)bh * N_SEQ + n) * 64 + d0)     = make_float2(v0, v1);
                *(float2*)(g_V + ((size_t)bh * N_SEQ + n + 8) * 64 + d0) = make_float2(v2, v3);
            }
        }
    }
}

// ======================= scores kernel (3xTF32, Q in registers) =======================
// S[q,:] = scaled Q K^T (scale folded into Q).  CTA: (bh, 128 q), 64 token-tiles
// of 32, double-buffered K. Q fragments live in registers (loaded once; loop-
// invariant over all k-tiles) -> no sQ smem, 33% fewer LDS in the inner loop.
// Emits per-row max into g_rowmax (fused, ~free).
#define SC_SMEM (2 * 32 * 144 * 4)   // 36,864 B

__global__ __launch_bounds__(256, 2)
void scores_kernel(float* __restrict__ S)
{
    extern __shared__ float sm[];
    float* sK[2] = { sm, sm + 32 * 144 };
    uint32_t sKa[2] = { smem_u32(sK[0]), smem_u32(sK[1]) };

    const int tid = threadIdx.x;
    const int bh = blockIdx.y, q0 = blockIdx.x * 128;
    const int w = tid >> 5, lane = tid & 31;
    const int g = lane >> 2, t4 = lane & 3;

    const size_t grow0 = (size_t)bh * N_SEQ + q0 + w * 16 + g;
    const size_t grow1 = grow0 + 8;

    // ---- Q fragments -> registers (once; loop-invariant) ----
    uint32_t ah[8][4], al[8][4];
    {
        const float* q0p = g_Qi + grow0 * 128;
        const float* q1p = g_Qi + grow1 * 128;
#pragma unroll
        for (int kf = 0; kf < 8; kf++) {
            float4 qa = *(const float4*)(q0p + kf * 16 + t4 * 4);
            float4 qb = *(const float4*)(q1p + kf * 16 + t4 * 4);
            ah[kf][0] = __float_as_uint(qa.x); ah[kf][1] = __float_as_uint(qb.x);
            ah[kf][2] = __float_as_uint(qa.y); ah[kf][3] = __float_as_uint(qb.y);
            al[kf][0] = __float_as_uint(qa.z); al[kf][1] = __float_as_uint(qb.z);
            al[kf][2] = __float_as_uint(qa.w); al[kf][3] = __float_as_uint(qb.w);
        }
    }

    const int lrK = tid >> 3, lcK = (tid & 7) * 16;   // 32 rows x 128 floats
    const float* krow = g_Ki + ((size_t)bh * N_SEQ + lrK) * 128 + lcK;
    auto prefetchK = [&](int kt, int buf) {
        const size_t off = (size_t)kt * 32 * 128;
#pragma unroll
        for (int i = 0; i < 4; i++)
            cp16(sKa[buf] + (lrK * 144 + lcK + i * 4) * 4, krow + off + i * 4);
        CP_COMMIT();
    };

    float m0 = -3.402823466e38f, m1 = -3.402823466e38f;   // row maxima

    prefetchK(0, 0);
    for (int kt = 0; kt < 64; kt++) {
        const int buf = kt & 1;
        if (kt < 63) { prefetchK(kt + 1, buf ^ 1); CP_WAIT(1); }
        else         { CP_WAIT(0); }
        __syncthreads();

        float acc[4][4];
#pragma unroll
        for (int i = 0; i < 4; i++)
#pragma unroll
            for (int j = 0; j < 4; j++) acc[i][j] = 0.f;

#pragma unroll
        for (int kf = 0; kf < 8; kf++) {
#pragma unroll
            for (int nf = 0; nf < 4; nf++) {
                float4 kb = *(const float4*)&sK[buf][(nf * 8 + g) * 144 + kf * 16 + t4 * 4];
                uint32_t bh2[2] = { __float_as_uint(kb.x), __float_as_uint(kb.y) };
                uint32_t bl2[2] = { __float_as_uint(kb.z), __float_as_uint(kb.w) };
                mma3(acc[nf], ah[kf], al[kf], bh2, bl2);
            }
        }
        __syncthreads();   // all warps done with sK[buf] before it is refilled

        float* dst0 = S + grow0 * N_SEQ + kt * 32;
        float* dst1 = S + grow1 * N_SEQ + kt * 32;
#pragma unroll
        for (int nf = 0; nf < 4; nf++) {
            m0 = fmaxf(m0, fmaxf(acc[nf][0], acc[nf][1]));
            m1 = fmaxf(m1, fmaxf(acc[nf][2], acc[nf][3]));
            const int c = nf * 8 + t4 * 2;
            *(float2*)(dst0 + c) = make_float2(acc[nf][0], acc[nf][1]);
            *(float2*)(dst1 + c) = make_float2(acc[nf][2], acc[nf][3]);
        }
    }

    m0 = fmaxf(m0, __shfl_xor_sync(0xffffffffu, m0, 1));
    m0 = fmaxf(m0, __shfl_xor_sync(0xffffffffu, m0, 2));
    m1 = fmaxf(m1, __shfl_xor_sync(0xffffffffu, m1, 1));
    m1 = fmaxf(m1, __shfl_xor_sync(0xffffffffu, m1, 2));
    if (t4 == 0) {
        g_rowmax[grow0] = m0;
        g_rowmax[grow1] = m1;
    }
}

// ======================= sparsemax kernel (R15-proven v4) =======================
// Row per warp. Single read pass: filter candidates (> rowmax-1) into shared
// (value + index), Newton over <=8 register candidates -> tau. Writeback needs
// NO read: zeros + scatter. Emits compacted (idx, w) list. Dense fallback = -1.
__global__ __launch_bounds__(256)
void spmax_kernel(float* __restrict__ A)
{
    __shared__ float cv[8 * 8 * 32];
    __shared__ int   cx[8 * 8 * 32];
    const int lane = threadIdx.x & 31;
    const int warp = threadIdx.x >> 5;
    const size_t row = (size_t)blockIdx.x * 8 + warp;
    const float4* r4 = (const float4*)(A + row * N_SEQ);
    float4* w4 = (float4*)(A + row * N_SEQ);

    const float thr = g_rowmax[row] - 1.0f;

    float* cwv = cv + warp * 256 + lane;
    int*   cwx = cx + warp * 256 + lane;
    int cnt = 0;
#pragma unroll 4
    for (int i = 0; i < 16; i++) {
        float4 v = r4[i * 32 + lane];
        float e[4] = { v.x, v.y, v.z, v.w };
#pragma unroll
        for (int c = 0; c < 4; c++) {
            if (e[c] > thr) {
                if (cnt < 8) { cwv[cnt * 32] = e[c]; cwx[cnt * 32] = (i * 32 + lane) * 4 + c; }
                cnt++;
            }
        }
    }
    __syncwarp();

    float tau = thr;
    if (__ballot_sync(0xffffffffu, cnt > 8)) {
        for (int it = 0; it < 64; ++it) {
            float Ss = 0.f; int k = 0;
#pragma unroll 4
            for (int i = 0; i < 16; i++) {
                float4 v = r4[i * 32 + lane];
                float dd;
                dd = v.x - tau; if (dd > 0.f) { Ss += dd; k++; }
                dd = v.y - tau; if (dd > 0.f) { Ss += dd; k++; }
                dd = v.z - tau; if (dd > 0.f) { Ss += dd; k++; }
                dd = v.w - tau; if (dd > 0.f) { Ss += dd; k++; }
            }
#pragma unroll
            for (int o = 16; o; o >>= 1) {
                Ss += __shfl_xor_sync(0xffffffffu, Ss, o);
                k  += __shfl_xor_sync(0xffffffffu, k, o);
            }
            if (k == 0) break;
            const float delta = (Ss - 1.0f) / (float)k;
            tau += delta;
            if (fabsf(delta) < 1e-8f) break;
        }
#pragma unroll 4
        for (int i = 0; i < 16; i++) {
            float4 v = r4[i * 32 + lane];
            float4 o;
            o.x = fmaxf(v.x - tau, 0.f); o.y = fmaxf(v.y - tau, 0.f);
            o.z = fmaxf(v.z - tau, 0.f); o.w = fmaxf(v.w - tau, 0.f);
            w4[i * 32 + lane] = o;
        }
        if (lane == 0) g_cn[row] = -1;
    } else {
        float cb[8];
#pragma unroll
        for (int j = 0; j < 8; j++) cb[j] = cwv[j * 32];
        for (int it = 0; it < 64; ++it) {
            float Ss = 0.f; int k = 0;
#pragma unroll
            for (int j = 0; j < 8; j++) {
                float dd = cb[j] - tau;
                if (j < cnt && dd > 0.f) { Ss += dd; k++; }
            }
#pragma unroll
            for (int o = 16; o; o >>= 1) {
                Ss += __shfl_xor_sync(0xffffffffu, Ss, o);
                k  += __shfl_xor_sync(0xffffffffu, k, o);
            }
            if (k == 0) break;
            const float delta = (Ss - 1.0f) / (float)k;
            tau += delta;
            if (fabsf(delta) < 1e-8f) break;
        }

        int incl = cnt;
#pragma unroll
        for (int o = 1; o < 32; o <<= 1) {
            int t = __shfl_up_sync(0xffffffffu, incl, o);
            if (lane >= o) incl += t;
        }
        const int excl = incl - cnt;
        const int total = __shfl_sync(0xffffffffu, incl, 31);
        const size_t base = row * 256;
#pragma unroll
        for (int j = 0; j < 8; j++) {
            if (j < cnt) {
                g_cw[base + excl + j] = fmaxf(cb[j] - tau, 0.f);
                g_ci[base + excl + j] = cwx[j * 32];
            }
        }
        if (lane == 0) g_cn[row] = total;

        const float4 z = make_float4(0.f, 0.f, 0.f, 0.f);
#pragma unroll 4
        for (int i = 0; i < 16; i++) w4[i * 32 + lane] = z;
#pragma unroll
        for (int j = 0; j < 8; j++) {
            if (j < cnt)
                A[row * N_SEQ + cwx[j * 32]] = fmaxf(cb[j] - tau, 0.f);
        }
    }
}

// ======================= sparse attn@V gather =======================
__global__ __launch_bounds__(256)
void spav_kernel(const float* __restrict__ A)
{
    const int lane = threadIdx.x & 31;
    const int warp = threadIdx.x >> 5;
    const size_t row = (size_t)blockIdx.x * 8 + warp;
    const int bh = (int)(row >> 11), q = (int)(row & 2047);
    const float* Vb = g_V + ((size_t)bh * N_SEQ) * 64;
    const int d = lane * 2;

    float ax = 0.f, ay = 0.f;
    const int n = g_cn[row];
    if (n >= 0) {
        const int*   ci = g_ci + row * 256;
        const float* cw = g_cw + row * 256;
        int j = 0;
        for (; j + 4 <= n; j += 4) {
            int   i0 = ci[j], i1 = ci[j+1], i2 = ci[j+2], i3 = ci[j+3];
            float w0 = cw[j], w1 = cw[j+1], w2 = cw[j+2], w3 = cw[j+3];
            float2 v0 = *(const float2*)(Vb + (size_t)i0 * 64 + d);
            float2 v1 = *(const float2*)(Vb + (size_t)i1 * 64 + d);
            float2 v2 = *(const float2*)(Vb + (size_t)i2 * 64 + d);
            float2 v3 = *(const float2*)(Vb + (size_t)i3 * 64 + d);
            ax += w0 * v0.x + w1 * v1.x + w2 * v2.x + w3 * v3.x;
            ay += w0 * v0.y + w1 * v1.y + w2 * v2.y + w3 * v3.y;
        }
        for (; j < n; j++) {
            int i0 = ci[j]; float w0 = cw[j];
            float2 v0 = *(const float2*)(Vb + (size_t)i0 * 64 + d);
            ax += w0 * v0.x; ay += w0 * v0.y;
        }
    } else {
        const float* Arow = A + row * N_SEQ;
        for (int k = 0; k < N_SEQ; k++) {
            float a = Arow[k];
            if (a != 0.f) {
                float2 v = *(const float2*)(Vb + (size_t)k * 64 + d);
                ax += a * v.x; ay += a * v.y;
            }
        }
    }

    const int b = bh >> 3, h = bh & 7;
    *(float2*)(g_P + ((size_t)(b * N_SEQ + q)) * C_DIM + h * 64 + d) = make_float2(ax, ay);
}

// ---------------------------------------------------------------------------
extern "C" void kernel_launch(void* const* d_in, const int* in_sizes, int n_in,
                              void* d_out, int out_size)
{
    const float* x  = (const float*)d_in[0];
    const float* Wq = (const float*)d_in[1];
    const float* bq = (const float*)d_in[2];
    const float* Wk = (const float*)d_in[3];
    const float* bk = (const float*)d_in[4];
    const float* Wv = (const float*)d_in[5];
    const float* bv = (const float*)d_in[6];
    const float* Wo = (const float*)d_in[7];
    const float* bo = (const float*)d_in[8];

    float *dP, *dS;
    cudaGetSymbolAddress((void**)&dP, g_P);
    cudaGetSymbolAddress((void**)&dS, g_S);

    float* out = (float*)d_out;
    const long long OUT_N = 2LL * N_SEQ * C_DIM;
    const long long ATT_N = (long long)N_BH * N_SEQ * N_SEQ;
    float* final_ptr = nullptr;
    float* attn_ptr  = nullptr;
    if ((long long)out_size >= OUT_N + ATT_N) { final_ptr = out; attn_ptr = out + OUT_N; }
    else if ((long long)out_size >= ATT_N)    { attn_ptr = out; }
    else                                      { final_ptr = out; }
    float* S = attn_ptr ? attn_ptr : dS;

    cudaFuncSetAttribute(proj_kernel,   cudaFuncAttributeMaxDynamicSharedMemorySize, PJ_SMEM);
    cudaFuncSetAttribute(scores_kernel, cudaFuncAttributeMaxDynamicSharedMemorySize, SC_SMEM);

    // pre-split weights into hi/lo interleaved; mats: 0=Wq 1=Wk 2=Wv 3=Wo
    wconv_kernel<<<dim3(C_DIM, 4), 128>>>(Wq, Wk, Wv, Wo);

    // Q/K/V projections in one launch (z selects weight + epilogue format)
    proj_kernel<<<dim3(32, 8, 3), 256, PJ_SMEM>>>(x, bq, bk, bv, bo, nullptr, 0);

    scores_kernel<<<dim3(16, 16), 256, SC_SMEM>>>(S);
    spmax_kernel<<<(N_BH * N_SEQ) / 8, 256>>>(S);
    spav_kernel<<<(N_BH * N_SEQ) / 8, 256>>>(S);

    if (final_ptr)
        proj_kernel<<<dim3(32, 8, 1), 256, PJ_SMEM>>>(dP, bq, bk, bv, bo, final_ptr, 3);
}